// round 4
// baseline (speedup 1.0000x reference)
#include <cuda_runtime.h>
#include <cuda_bf16.h>
#include <math.h>

#define T_TOK 2048
#define D_DIM 2048
#define N_H   16
#define N_KVH 4
#define HD    128
#define N_E   8
#define I_DIM 1024

// ---------------- scratch (static device globals; allocation-free) ----------------
__device__ float g_xnorm[T_TOK * D_DIM];
__device__ float g_q[T_TOK * N_H * HD];
__device__ float g_k[T_TOK * N_KVH * HD];
__device__ float g_v[T_TOK * N_KVH * HD];
__device__ float g_attn[T_TOK * N_H * HD];
__device__ float g_x2[T_TOK * D_DIM];
__device__ float g_gbuf[T_TOK * I_DIM];
__device__ float g_ubuf[T_TOK * I_DIM];
__device__ float g_comb[T_TOK * N_E];
__device__ float g_scores[(size_t)N_H * T_TOK * T_TOK];   // 268 MB scratch

// ---------------- RMSNorm (rewritten: strided scalar + smem tree) ----------------
__global__ void rmsnorm2_kernel(const float* __restrict__ x, const float* __restrict__ w,
                                float* __restrict__ out) {
    int row = blockIdx.x, tid = threadIdx.x;
    const float* xr = x + (size_t)row * D_DIM;
    float ss = 0.f;
    for (int i = tid; i < D_DIM; i += 256) {
        float v = xr[i];
        ss = fmaf(v, v, ss);
    }
    __shared__ float sred[256];
    sred[tid] = ss;
    __syncthreads();
    for (int st = 128; st; st >>= 1) {
        if (tid < st) sred[tid] += sred[tid + st];
        __syncthreads();
    }
    float inv = rsqrtf(sred[0] * (1.0f / D_DIM) + 1e-6f);
    for (int i = tid; i < D_DIM; i += 256)
        out[(size_t)row * D_DIM + i] = xr[i] * inv * w[i];
}

// ---------------- naive GEMM: C[m][n] = sum_k A[m][k] * B[k][n] ----------------
// EPI: 0 = +bias[n], 1 = +res[m][n], 2 = plain, 3 = C += w[m*ws+wo]*acc
template <int EPI>
__global__ void __launch_bounds__(256)
ngemm_kernel(const float* __restrict__ A, const float* __restrict__ B, float* __restrict__ C,
             int M, int N, int K,
             const float* __restrict__ bias, const float* __restrict__ res,
             const float* __restrict__ w, int wstride, int woff) {
    int n = blockIdx.x * 256 + threadIdx.x;
    int m = blockIdx.y;
    if (n >= N || m >= M) return;
    const float* ar = A + (size_t)m * K;
    const float* bp = B + n;
    float acc = 0.f;
#pragma unroll 8
    for (int k = 0; k < K; ++k)
        acc = fmaf(__ldg(ar + k), __ldg(bp + (size_t)k * N), acc);
    size_t idx = (size_t)m * N + n;
    if (EPI == 0)      C[idx] = acc + bias[n];
    else if (EPI == 1) C[idx] = acc + res[idx];
    else if (EPI == 2) C[idx] = acc;
    else               C[idx] += w[m * wstride + woff] * acc;
}

// ---------------- RoPE (rewritten: f32 freq, double trig) ----------------
__global__ void rope2_kernel(float* __restrict__ x, const int* __restrict__ pos, int nheads) {
    int t = blockIdx.x;
    float p = (float)pos[t];
    for (int idx = threadIdx.x; idx < nheads * 64; idx += blockDim.x) {
        int h = idx >> 6, i = idx & 63;
        float invf = (float)exp(-(double)i * (13.815510557964274 / 64.0));
        float fr = p * invf;                 // f32 freq, matching reference
        double cd = cos((double)fr), sd = sin((double)fr);  // exact trig
        float c = (float)cd, s = (float)sd;
        float* b = x + ((size_t)t * nheads + h) * HD;
        float x1 = b[i], x2 = b[i + 64];
        b[i] = x1 * c - x2 * s;
        b[i + 64] = x2 * c + x1 * s;
    }
}

// ---------------- brute-force attention: QK -> softmax -> PV ----------------
__global__ void qk_kernel(const float* __restrict__ q, const float* __restrict__ k,
                          float* __restrict__ scores) {
    int t = blockIdx.x, h = blockIdx.y;
    __shared__ float qs[HD];
    if (threadIdx.x < HD) qs[threadIdx.x] = q[(size_t)t * (N_H * HD) + h * HD + threadIdx.x];
    __syncthreads();
    const float* kb = k + (h >> 2) * HD;
    float* srow = scores + ((size_t)h * T_TOK + t) * T_TOK;
    const float scale = 0.08838834764831845f;
    for (int s = threadIdx.x; s <= t; s += blockDim.x) {
        const float* kr = kb + (size_t)s * (N_KVH * HD);
        float acc = 0.f;
#pragma unroll 16
        for (int d = 0; d < HD; ++d) acc = fmaf(qs[d], kr[d], acc);
        srow[s] = acc * scale;
    }
}

__global__ void softmax_kernel(float* __restrict__ scores) {
    int t = blockIdx.x, h = blockIdx.y, tid = threadIdx.x;
    float* srow = scores + ((size_t)h * T_TOK + t) * T_TOK;
    int n = t + 1;
    __shared__ float sred[256];
    float mx = -INFINITY;
    for (int s = tid; s < n; s += 256) mx = fmaxf(mx, srow[s]);
    sred[tid] = mx;
    __syncthreads();
    for (int st = 128; st; st >>= 1) {
        if (tid < st) sred[tid] = fmaxf(sred[tid], sred[tid + st]);
        __syncthreads();
    }
    mx = sred[0];
    __syncthreads();
    float sum = 0.f;
    for (int s = tid; s < n; s += 256) {
        float e = expf(srow[s] - mx);
        srow[s] = e;
        sum += e;
    }
    sred[tid] = sum;
    __syncthreads();
    for (int st = 128; st; st >>= 1) {
        if (tid < st) sred[tid] += sred[tid + st];
        __syncthreads();
    }
    float inv = 1.f / sred[0];
    for (int s = tid; s < n; s += 256) srow[s] *= inv;
}

__global__ void pv_kernel(const float* __restrict__ scores, const float* __restrict__ v,
                          float* __restrict__ o) {
    int t = blockIdx.x, h = blockIdx.y, d = threadIdx.x;  // 128 threads
    const float* srow = scores + ((size_t)h * T_TOK + t) * T_TOK;
    const float* vb = v + (h >> 2) * HD + d;
    float acc = 0.f;
    for (int s = 0; s <= t; ++s)
        acc = fmaf(srow[s], vb[(size_t)s * (N_KVH * HD)], acc);
    o[(size_t)t * (N_H * HD) + h * HD + d] = acc;
}

// ---------------- naive router: one thread per token, dense comb[T][E] ----------------
__global__ void router_naive_kernel(const float* __restrict__ x, const float* __restrict__ gw,
                                    float* __restrict__ comb) {
    int t = blockIdx.x * blockDim.x + threadIdx.x;
    if (t >= T_TOK) return;
    const float* xr = x + (size_t)t * D_DIM;
    float l[8] = {0, 0, 0, 0, 0, 0, 0, 0};
    for (int d = 0; d < D_DIM; ++d) {
        float xv = xr[d];
        const float* gr = gw + (size_t)d * N_E;
#pragma unroll
        for (int e = 0; e < 8; ++e) l[e] = fmaf(xv, __ldg(gr + e), l[e]);
    }
    float mx = l[0];
#pragma unroll
    for (int e = 1; e < 8; ++e) mx = fmaxf(mx, l[e]);
    float p[8], ssum = 0.f;
#pragma unroll
    for (int e = 0; e < 8; ++e) { p[e] = expf(l[e] - mx); ssum += p[e]; }
#pragma unroll
    for (int e = 0; e < 8; ++e) p[e] /= ssum;
    int i0 = 0; float p0 = p[0];
#pragma unroll
    for (int e = 1; e < 8; ++e) if (p[e] > p0) { p0 = p[e]; i0 = e; }
    int i1 = -1; float p1 = -1.f;
#pragma unroll
    for (int e = 0; e < 8; ++e) if (e != i0 && p[e] > p1) { p1 = p[e]; i1 = e; }
    float wn = p0 + p1;
#pragma unroll
    for (int e = 0; e < 8; ++e)
        comb[t * N_E + e] = (e == i0) ? (p0 / wn) : ((e == i1) ? (p1 / wn) : 0.f);
}

// ---------------- silu(g)*u in place (into g) ----------------
__global__ void silu_mul_kernel(float* __restrict__ g, const float* __restrict__ u, int n) {
    int i = blockIdx.x * blockDim.x + threadIdx.x;
    if (i >= n) return;
    float gv = g[i], uv = u[i];
    g[i] = gv / (1.f + expf(-gv)) * uv;
}

// ---------------- launch ----------------
extern "C" void kernel_launch(void* const* d_in, const int* in_sizes, int n_in,
                              void* d_out, int out_size) {
    const float* hidden = (const float*)d_in[0];
    const int* positions = (const int*)d_in[1];
    const float* ln1 = (const float*)d_in[2];
    const float* ln2 = (const float*)d_in[3];
    const float* wq = (const float*)d_in[4];
    const float* bq = (const float*)d_in[5];
    const float* wk = (const float*)d_in[6];
    const float* bk = (const float*)d_in[7];
    const float* wv = (const float*)d_in[8];
    const float* bv = (const float*)d_in[9];
    const float* wo = (const float*)d_in[10];
    const float* gate_w = (const float*)d_in[11];
    const float* w_gate = (const float*)d_in[12];
    const float* w_up = (const float*)d_in[13];
    const float* w_down = (const float*)d_in[14];
    float* out = (float*)d_out;

    float *xnorm, *q, *k, *v, *attn, *x2, *gbuf, *ubuf, *comb, *scores;
    cudaGetSymbolAddress((void**)&xnorm, g_xnorm);
    cudaGetSymbolAddress((void**)&q, g_q);
    cudaGetSymbolAddress((void**)&k, g_k);
    cudaGetSymbolAddress((void**)&v, g_v);
    cudaGetSymbolAddress((void**)&attn, g_attn);
    cudaGetSymbolAddress((void**)&x2, g_x2);
    cudaGetSymbolAddress((void**)&gbuf, g_gbuf);
    cudaGetSymbolAddress((void**)&ubuf, g_ubuf);
    cudaGetSymbolAddress((void**)&comb, g_comb);
    cudaGetSymbolAddress((void**)&scores, g_scores);

    // 1) RMSNorm 1
    rmsnorm2_kernel<<<T_TOK, 256>>>(hidden, ln1, xnorm);
    // 2) QKV projections (+bias), naive GEMM
    ngemm_kernel<0><<<dim3(8, T_TOK), 256>>>(xnorm, wq, q, T_TOK, 2048, 2048,
                                             bq, nullptr, nullptr, 0, 0);
    ngemm_kernel<0><<<dim3(2, T_TOK), 256>>>(xnorm, wk, k, T_TOK, 512, 2048,
                                             bk, nullptr, nullptr, 0, 0);
    ngemm_kernel<0><<<dim3(2, T_TOK), 256>>>(xnorm, wv, v, T_TOK, 512, 2048,
                                             bv, nullptr, nullptr, 0, 0);
    // 3) RoPE (double-precision trig)
    rope2_kernel<<<T_TOK, 256>>>(q, positions, N_H);
    rope2_kernel<<<T_TOK, 256>>>(k, positions, N_KVH);
    // 4) brute-force attention
    qk_kernel<<<dim3(T_TOK, N_H), 256>>>(q, k, scores);
    softmax_kernel<<<dim3(T_TOK, N_H), 256>>>(scores);
    pv_kernel<<<dim3(T_TOK, N_H), 128>>>(scores, v, attn);
    // 5) output proj + residual -> d_out holds h
    ngemm_kernel<1><<<dim3(8, T_TOK), 256>>>(attn, wo, out, T_TOK, 2048, 2048,
                                             nullptr, hidden, nullptr, 0, 0);
    // 6) RMSNorm 2
    rmsnorm2_kernel<<<T_TOK, 256>>>(out, ln2, x2);
    // 7) router -> dense comb
    router_naive_kernel<<<T_TOK / 256, 256>>>(x2, gate_w, comb);
    // 8) dense MoE, one expert at a time, accumulate weighted into d_out
    for (int e = 0; e < N_E; ++e) {
        const float* wg = w_gate + (size_t)e * D_DIM * I_DIM;
        const float* wu = w_up + (size_t)e * D_DIM * I_DIM;
        const float* wd = w_down + (size_t)e * I_DIM * D_DIM;
        ngemm_kernel<2><<<dim3(4, T_TOK), 256>>>(x2, wg, gbuf, T_TOK, I_DIM, D_DIM,
                                                 nullptr, nullptr, nullptr, 0, 0);
        ngemm_kernel<2><<<dim3(4, T_TOK), 256>>>(x2, wu, ubuf, T_TOK, I_DIM, D_DIM,
                                                 nullptr, nullptr, nullptr, 0, 0);
        silu_mul_kernel<<<(T_TOK * I_DIM + 255) / 256, 256>>>(gbuf, ubuf, T_TOK * I_DIM);
        ngemm_kernel<3><<<dim3(8, T_TOK), 256>>>(gbuf, wd, out, T_TOK, D_DIM, I_DIM,
                                                 nullptr, nullptr, comb, N_E, e);
    }
}

// round 5
// speedup vs baseline: 8.6809x; 8.6809x over previous
#include <cuda_runtime.h>
#include <cuda_bf16.h>
#include <math.h>

#define T_TOK 2048
#define D_DIM 2048
#define N_H   16
#define N_KVH 4
#define HD    128
#define N_E   8
#define I_DIM 1024

// ---------------- scratch (static device globals; allocation-free) ----------------
__device__ float g_xnorm[T_TOK * D_DIM];
__device__ float g_q[T_TOK * N_H * HD];
__device__ float g_k[T_TOK * N_KVH * HD];
__device__ float g_v[T_TOK * N_KVH * HD];
__device__ float g_attn[T_TOK * N_H * HD];
__device__ float g_x2[T_TOK * D_DIM];
__device__ float g_gbuf[N_E * T_TOK * I_DIM];
__device__ float g_ubuf[N_E * T_TOK * I_DIM];
__device__ int   g_cnt[N_E];
__device__ int   g_tok[N_E * T_TOK];
__device__ float g_wt[N_E * T_TOK];
__device__ float g_cos[T_TOK * 64];
__device__ float g_sin[T_TOK * 64];

// ---------------- RMSNorm ----------------
__global__ void rmsnorm_kernel(const float* __restrict__ x, const float* __restrict__ w,
                               float* __restrict__ out) {
    int row = blockIdx.x, tid = threadIdx.x;
    const float4* xr = (const float4*)(x + (size_t)row * D_DIM);
    const float4* wr = (const float4*)w;
    float ss = 0.f;
#pragma unroll
    for (int p = 0; p < 2; ++p) {
        float4 v = xr[tid + p * 256];
        ss += v.x * v.x + v.y * v.y + v.z * v.z + v.w * v.w;
    }
#pragma unroll
    for (int o = 16; o; o >>= 1) ss += __shfl_xor_sync(0xffffffffu, ss, o);
    __shared__ float red[8];
    if ((tid & 31) == 0) red[tid >> 5] = ss;
    __syncthreads();
    float tot = 0.f;
#pragma unroll
    for (int i = 0; i < 8; ++i) tot += red[i];
    float inv = rsqrtf(tot * (1.0f / D_DIM) + 1e-6f);
    float4* o4 = (float4*)(out + (size_t)row * D_DIM);
#pragma unroll
    for (int p = 0; p < 2; ++p) {
        int i = tid + p * 256;
        float4 v = xr[i], wv = wr[i];
        o4[i] = make_float4(v.x * inv * wv.x, v.y * inv * wv.y,
                            v.z * inv * wv.z, v.w * inv * wv.w);
    }
}

// ---------------- tiled 128x128 SGEMM ----------------
// EPI: 0 = +bias store, 1 = +residual store, 2 = plain store, 3 = atomic scatter *weight
template <int EPI, bool GATHER>
__global__ void __launch_bounds__(256)
gemm_kernel(const float* __restrict__ A, const float* __restrict__ B, float* __restrict__ C,
            int M, int N, int Kd,
            const float* __restrict__ bias, const float* __restrict__ res,
            const int* __restrict__ cnt, const int* __restrict__ tok,
            const float* __restrict__ wt,
            long aBatch, long bBatch, long cBatch) {
    __shared__ float As[16 * 128];
    __shared__ float Bs[16 * 128];
    const int e = blockIdx.z;
    const int Mcur = cnt ? cnt[e] : M;
    const int m0 = blockIdx.y * 128;
    if (m0 >= Mcur) return;
    const int n0 = blockIdx.x * 128;
    const float* Ab = A + (size_t)e * aBatch;
    const float* Bb = B + (size_t)e * bBatch;
    float* Cb = C + (size_t)e * cBatch;
    const int* tokb = tok ? tok + e * T_TOK : nullptr;
    const int tid = threadIdx.x, tx = tid & 15, ty = tid >> 4;

    const int lr0 = tid >> 2;
    const int lc4 = (tid & 3) << 2;
    int arow[2];
    bool av[2];
#pragma unroll
    for (int p = 0; p < 2; ++p) {
        int rg = m0 + lr0 + p * 64;
        av[p] = rg < Mcur;
        arow[p] = av[p] ? (GATHER ? tokb[rg] : rg) : 0;
    }

    float acc[8][8];
#pragma unroll
    for (int i = 0; i < 8; ++i)
#pragma unroll
        for (int j = 0; j < 8; ++j) acc[i][j] = 0.f;

    for (int kk = 0; kk < Kd; kk += 16) {
#pragma unroll
        for (int p = 0; p < 2; ++p) {
            float4 va = make_float4(0.f, 0.f, 0.f, 0.f);
            if (av[p]) va = *(const float4*)(Ab + (size_t)arow[p] * Kd + kk + lc4);
            int r = lr0 + p * 64;
            As[(lc4 + 0) * 128 + r] = va.x;
            As[(lc4 + 1) * 128 + r] = va.y;
            As[(lc4 + 2) * 128 + r] = va.z;
            As[(lc4 + 3) * 128 + r] = va.w;
        }
#pragma unroll
        for (int p = 0; p < 2; ++p) {
            int idx = tid + p * 256;
            int r = idx >> 5, c4 = (idx & 31) << 2;
            *(float4*)&Bs[r * 128 + c4] = *(const float4*)(Bb + (size_t)(kk + r) * N + n0 + c4);
        }
        __syncthreads();
#pragma unroll
        for (int kq = 0; kq < 16; ++kq) {
            float4 a0 = *(const float4*)&As[kq * 128 + ty * 8];
            float4 a1 = *(const float4*)&As[kq * 128 + ty * 8 + 4];
            float4 b0 = *(const float4*)&Bs[kq * 128 + tx * 8];
            float4 b1 = *(const float4*)&Bs[kq * 128 + tx * 8 + 4];
            float ra[8] = {a0.x, a0.y, a0.z, a0.w, a1.x, a1.y, a1.z, a1.w};
            float rb[8] = {b0.x, b0.y, b0.z, b0.w, b1.x, b1.y, b1.z, b1.w};
#pragma unroll
            for (int i = 0; i < 8; ++i)
#pragma unroll
                for (int j = 0; j < 8; ++j) acc[i][j] = fmaf(ra[i], rb[j], acc[i][j]);
        }
        __syncthreads();
    }

#pragma unroll
    for (int i = 0; i < 8; ++i) {
        int rg = m0 + ty * 8 + i;
        if (rg >= Mcur) continue;
        if (EPI == 3) {
            int t = tokb[rg];
            float w = wt[e * T_TOK + rg];
            float* outr = C + (size_t)t * N + n0 + tx * 8;
#pragma unroll
            for (int j = 0; j < 8; ++j) atomicAdd(&outr[j], acc[i][j] * w);
        } else {
            float v[8];
#pragma unroll
            for (int j = 0; j < 8; ++j) v[j] = acc[i][j];
            if (EPI == 0) {
                const float* br = bias + n0 + tx * 8;
#pragma unroll
                for (int j = 0; j < 8; ++j) v[j] += br[j];
            }
            if (EPI == 1) {
                const float* rr = res + (size_t)rg * N + n0 + tx * 8;
#pragma unroll
                for (int j = 0; j < 8; ++j) v[j] += rr[j];
            }
            float* cr = Cb + (size_t)rg * N + n0 + tx * 8;
            *(float4*)cr = make_float4(v[0], v[1], v[2], v[3]);
            *(float4*)(cr + 4) = make_float4(v[4], v[5], v[6], v[7]);
        }
    }
}

// ---------------- RoPE: accurate table (double trig) + f32 apply ----------------
__global__ void rope_table_kernel(const int* __restrict__ pos,
                                  float* __restrict__ ctab, float* __restrict__ stab) {
    int t = blockIdx.x, i = threadIdx.x;  // 64 threads
    float p = (float)pos[t];
    float invf = (float)exp(-(double)i * (13.815510557964274 / 64.0));
    float fr = p * invf;                     // f32 freq (matches reference)
    double cd = cos((double)fr), sd = sin((double)fr);
    ctab[t * 64 + i] = (float)cd;
    stab[t * 64 + i] = (float)sd;
}

__global__ void rope_apply_kernel(float* __restrict__ x, const float* __restrict__ ctab,
                                  const float* __restrict__ stab, int nheads) {
    int t = blockIdx.x, h = blockIdx.y, i = threadIdx.x;  // 64 threads
    float c = ctab[t * 64 + i], s = stab[t * 64 + i];
    float* b = x + ((size_t)t * nheads + h) * HD;
    float x1 = b[i], x2 = b[i + 64];
    b[i] = x1 * c - x2 * s;
    b[i + 64] = x2 * c + x1 * s;
}

// ---------------- flash attention v2 (validated) ----------------
#define F2_QSTR 129
#define F2_SSTR 65
__global__ void __launch_bounds__(256)
flash2_kernel(const float* __restrict__ q, const float* __restrict__ k,
              const float* __restrict__ v, float* __restrict__ o) {
    extern __shared__ float sm2[];
    float* Qs = sm2;
    float* Ks = sm2 + 64 * F2_QSTR;
    float* Ss = sm2 + 2 * 64 * F2_QSTR;
    const int tid = threadIdx.x;
    const int r = tid >> 2;
    const int g = tid & 3;
    const int qt = blockIdx.x, head = blockIdx.y, kvh = head >> 2;
    const int qr0 = qt * 64;
    const float scale = 0.08838834764831845f;

    for (int it = tid; it < 2048; it += 256) {
        int rr = it >> 5, c4 = (it & 31) << 2;
        float4 vq = *(const float4*)(q + (size_t)(qr0 + rr) * (N_H * HD) + head * HD + c4);
        float* dst = Qs + rr * F2_QSTR + c4;
        dst[0] = vq.x; dst[1] = vq.y; dst[2] = vq.z; dst[3] = vq.w;
    }
    float oacc[32];
#pragma unroll
    for (int c = 0; c < 32; ++c) oacc[c] = 0.f;
    float mrow = -INFINITY, lrow = 0.f;
    __syncthreads();

    for (int kt = 0; kt <= qt; ++kt) {
        const int kr0 = kt * 64;
        for (int it = tid; it < 2048; it += 256) {
            int rr = it >> 5, c4 = (it & 31) << 2;
            float4 vk = *(const float4*)(k + (size_t)(kr0 + rr) * (N_KVH * HD) + kvh * HD + c4);
            float* dst = Ks + rr * F2_QSTR + c4;
            dst[0] = vk.x; dst[1] = vk.y; dst[2] = vk.z; dst[3] = vk.w;
        }
        __syncthreads();
        float s[16];
#pragma unroll
        for (int jj = 0; jj < 16; ++jj) s[jj] = 0.f;
        for (int d = 0; d < 128; ++d) {
            float qv = Qs[r * F2_QSTR + d];
#pragma unroll
            for (int jj = 0; jj < 16; ++jj)
                s[jj] = fmaf(qv, Ks[(g * 16 + jj) * F2_QSTR + d], s[jj]);
        }
        float mx = -INFINITY;
#pragma unroll
        for (int jj = 0; jj < 16; ++jj) {
            int col = kr0 + g * 16 + jj;
            float sv = (col <= qr0 + r) ? s[jj] * scale : -INFINITY;
            s[jj] = sv;
            mx = fmaxf(mx, sv);
        }
        mx = fmaxf(mx, __shfl_xor_sync(0xffffffffu, mx, 1));
        mx = fmaxf(mx, __shfl_xor_sync(0xffffffffu, mx, 2));
        float nm = fmaxf(mrow, mx);
        float rs = 0.f;
#pragma unroll
        for (int jj = 0; jj < 16; ++jj) {
            float pv = expf(s[jj] - nm);
            s[jj] = pv;
            rs += pv;
        }
        rs += __shfl_xor_sync(0xffffffffu, rs, 1);
        rs += __shfl_xor_sync(0xffffffffu, rs, 2);
        float alpha = expf(mrow - nm);
        lrow = lrow * alpha + rs;
        mrow = nm;
#pragma unroll
        for (int jj = 0; jj < 16; ++jj) Ss[r * F2_SSTR + g * 16 + jj] = s[jj];
#pragma unroll
        for (int c = 0; c < 32; ++c) oacc[c] *= alpha;
        __syncthreads();
        for (int it = tid; it < 2048; it += 256) {
            int rr = it >> 5, c4 = (it & 31) << 2;
            float4 vv = *(const float4*)(v + (size_t)(kr0 + rr) * (N_KVH * HD) + kvh * HD + c4);
            float* dst = Ks + rr * F2_QSTR + c4;
            dst[0] = vv.x; dst[1] = vv.y; dst[2] = vv.z; dst[3] = vv.w;
        }
        __syncthreads();
        for (int j = 0; j < 64; ++j) {
            float pv = Ss[r * F2_SSTR + j];
            const float* vrow = Ks + j * F2_QSTR + g * 32;
#pragma unroll
            for (int cc = 0; cc < 32; ++cc) {
                int c = (cc + g * 8) & 31;
                oacc[cc] = fmaf(pv, vrow[c], oacc[cc]);
            }
        }
        __syncthreads();
    }
    float invl = 1.f / lrow;
    float* orow = o + (size_t)(qr0 + r) * (N_H * HD) + head * HD + g * 32;
#pragma unroll
    for (int cc = 0; cc < 32; ++cc) {
        int c = (cc + g * 8) & 31;
        orow[c] = oacc[cc] * invl;
    }
}

// ---------------- router: logits -> softmax -> top2 -> scatter ----------------
__global__ void router_kernel(const float* __restrict__ x, const float* __restrict__ gw,
                              int* __restrict__ cnt, int* __restrict__ tok,
                              float* __restrict__ wt) {
    int t = blockIdx.x;
    const float* xr = x + (size_t)t * D_DIM;
    float acc[8] = {0, 0, 0, 0, 0, 0, 0, 0};
    for (int d = threadIdx.x; d < D_DIM; d += 256) {
        float xv = xr[d];
        const float4* g4 = (const float4*)(gw + (size_t)d * N_E);
        float4 a = g4[0], b = g4[1];
        acc[0] = fmaf(xv, a.x, acc[0]); acc[1] = fmaf(xv, a.y, acc[1]);
        acc[2] = fmaf(xv, a.z, acc[2]); acc[3] = fmaf(xv, a.w, acc[3]);
        acc[4] = fmaf(xv, b.x, acc[4]); acc[5] = fmaf(xv, b.y, acc[5]);
        acc[6] = fmaf(xv, b.z, acc[6]); acc[7] = fmaf(xv, b.w, acc[7]);
    }
    __shared__ float smr[8][256];
#pragma unroll
    for (int e = 0; e < 8; ++e) smr[e][threadIdx.x] = acc[e];
    __syncthreads();
    for (int s = 128; s; s >>= 1) {
        if (threadIdx.x < s)
#pragma unroll
            for (int e = 0; e < 8; ++e) smr[e][threadIdx.x] += smr[e][threadIdx.x + s];
        __syncthreads();
    }
    if (threadIdx.x == 0) {
        float l[8], p[8];
        float mx = -1e30f;
#pragma unroll
        for (int e = 0; e < 8; ++e) { l[e] = smr[e][0]; mx = fmaxf(mx, l[e]); }
        float ssum = 0.f;
#pragma unroll
        for (int e = 0; e < 8; ++e) { p[e] = expf(l[e] - mx); ssum += p[e]; }
#pragma unroll
        for (int e = 0; e < 8; ++e) p[e] /= ssum;
        int i0 = 0; float p0 = p[0];
#pragma unroll
        for (int e = 1; e < 8; ++e) if (p[e] > p0) { p0 = p[e]; i0 = e; }
        int i1 = -1; float p1 = -1.f;
#pragma unroll
        for (int e = 0; e < 8; ++e) if (e != i0 && p[e] > p1) { p1 = p[e]; i1 = e; }
        float wn = p0 + p1;
        int pos = atomicAdd(&cnt[i0], 1);
        tok[i0 * T_TOK + pos] = t; wt[i0 * T_TOK + pos] = p0 / wn;
        pos = atomicAdd(&cnt[i1], 1);
        tok[i1 * T_TOK + pos] = t; wt[i1 * T_TOK + pos] = p1 / wn;
    }
}

// ---------------- silu(g)*u, only over active rows per expert ----------------
__global__ void silu_mul_kernel(float* __restrict__ g, const float* __restrict__ u,
                                const int* __restrict__ cnt) {
    int e = blockIdx.z;
    int row = blockIdx.y;
    if (row >= cnt[e]) return;
    size_t base = ((size_t)e * T_TOK + row) * I_DIM;
    int i = blockIdx.x * 256 + threadIdx.x;  // 0..255, I_DIM/4 = 256 float4
    float4 gv = ((const float4*)(g + base))[i];
    float4 uv = ((const float4*)(u + base))[i];
    gv.x = gv.x / (1.f + __expf(-gv.x)) * uv.x;
    gv.y = gv.y / (1.f + __expf(-gv.y)) * uv.y;
    gv.z = gv.z / (1.f + __expf(-gv.z)) * uv.z;
    gv.w = gv.w / (1.f + __expf(-gv.w)) * uv.w;
    ((float4*)(g + base))[i] = gv;
}

// ---------------- launch ----------------
extern "C" void kernel_launch(void* const* d_in, const int* in_sizes, int n_in,
                              void* d_out, int out_size) {
    const float* hidden = (const float*)d_in[0];
    const int* positions = (const int*)d_in[1];
    const float* ln1 = (const float*)d_in[2];
    const float* ln2 = (const float*)d_in[3];
    const float* wq = (const float*)d_in[4];
    const float* bq = (const float*)d_in[5];
    const float* wk = (const float*)d_in[6];
    const float* bk = (const float*)d_in[7];
    const float* wv = (const float*)d_in[8];
    const float* bv = (const float*)d_in[9];
    const float* wo = (const float*)d_in[10];
    const float* gate_w = (const float*)d_in[11];
    const float* w_gate = (const float*)d_in[12];
    const float* w_up = (const float*)d_in[13];
    const float* w_down = (const float*)d_in[14];
    float* out = (float*)d_out;

    float *xnorm, *q, *k, *v, *attn, *x2, *gbuf, *ubuf, *wt, *ctab, *stab;
    int *cnt, *tok;
    cudaGetSymbolAddress((void**)&xnorm, g_xnorm);
    cudaGetSymbolAddress((void**)&q, g_q);
    cudaGetSymbolAddress((void**)&k, g_k);
    cudaGetSymbolAddress((void**)&v, g_v);
    cudaGetSymbolAddress((void**)&attn, g_attn);
    cudaGetSymbolAddress((void**)&x2, g_x2);
    cudaGetSymbolAddress((void**)&gbuf, g_gbuf);
    cudaGetSymbolAddress((void**)&ubuf, g_ubuf);
    cudaGetSymbolAddress((void**)&cnt, g_cnt);
    cudaGetSymbolAddress((void**)&tok, g_tok);
    cudaGetSymbolAddress((void**)&wt, g_wt);
    cudaGetSymbolAddress((void**)&ctab, g_cos);
    cudaGetSymbolAddress((void**)&stab, g_sin);

    const int smem_flash = (2 * 64 * F2_QSTR + 64 * F2_SSTR) * sizeof(float);
    cudaFuncSetAttribute(flash2_kernel, cudaFuncAttributeMaxDynamicSharedMemorySize, smem_flash);

    // 0) RoPE table (accurate trig)
    rope_table_kernel<<<T_TOK, 64>>>(positions, ctab, stab);
    // 1) RMSNorm 1
    rmsnorm_kernel<<<T_TOK, 256>>>(hidden, ln1, xnorm);
    // 2) QKV projections (+bias)
    gemm_kernel<0, false><<<dim3(16, 16, 1), 256>>>(xnorm, wq, q, T_TOK, 2048, 2048,
                                                    bq, nullptr, nullptr, nullptr, nullptr, 0, 0, 0);
    gemm_kernel<0, false><<<dim3(4, 16, 1), 256>>>(xnorm, wk, k, T_TOK, 512, 2048,
                                                   bk, nullptr, nullptr, nullptr, nullptr, 0, 0, 0);
    gemm_kernel<0, false><<<dim3(4, 16, 1), 256>>>(xnorm, wv, v, T_TOK, 512, 2048,
                                                   bv, nullptr, nullptr, nullptr, nullptr, 0, 0, 0);
    // 3) RoPE apply
    rope_apply_kernel<<<dim3(T_TOK, N_H), 64>>>(q, ctab, stab, N_H);
    rope_apply_kernel<<<dim3(T_TOK, N_KVH), 64>>>(k, ctab, stab, N_KVH);
    // 4) attention
    flash2_kernel<<<dim3(T_TOK / 64, N_H), 256, smem_flash>>>(q, k, v, attn);
    // 5) output proj + residual -> d_out holds h
    gemm_kernel<1, false><<<dim3(16, 16, 1), 256>>>(attn, wo, out, T_TOK, 2048, 2048,
                                                    nullptr, hidden, nullptr, nullptr, nullptr, 0, 0, 0);
    // 6) RMSNorm 2
    rmsnorm_kernel<<<T_TOK, 256>>>(out, ln2, x2);
    // 7) router
    cudaMemsetAsync(cnt, 0, N_E * sizeof(int));
    router_kernel<<<T_TOK, 256>>>(x2, gate_w, cnt, tok, wt);
    // 8) expert gate/up GEMMs (gathered rows, early-exit on count)
    gemm_kernel<2, true><<<dim3(I_DIM / 128, T_TOK / 128, N_E), 256>>>(
        x2, w_gate, gbuf, 0, I_DIM, D_DIM, nullptr, nullptr, cnt, tok, nullptr,
        0, (long)D_DIM * I_DIM, (long)T_TOK * I_DIM);
    gemm_kernel<2, true><<<dim3(I_DIM / 128, T_TOK / 128, N_E), 256>>>(
        x2, w_up, ubuf, 0, I_DIM, D_DIM, nullptr, nullptr, cnt, tok, nullptr,
        0, (long)D_DIM * I_DIM, (long)T_TOK * I_DIM);
    // 9) silu(g)*u on active rows only
    silu_mul_kernel<<<dim3(1, T_TOK, N_E), 256>>>(gbuf, ubuf, cnt);
    // 10) expert down GEMM, scatter *weight into d_out (residual already there)
    gemm_kernel<3, false><<<dim3(D_DIM / 128, T_TOK / 128, N_E), 256>>>(
        gbuf, w_down, out, 0, D_DIM, I_DIM, nullptr, nullptr, cnt, tok, wt,
        (long)T_TOK * I_DIM, (long)I_DIM * D_DIM, 0);
}

// round 6
// speedup vs baseline: 9.7208x; 1.1198x over previous
#include <cuda_runtime.h>
#include <cuda_bf16.h>
#include <math.h>
#include <stdint.h>

#define T_TOK 2048
#define D_DIM 2048
#define N_H   16
#define N_KVH 4
#define HD    128
#define N_E   8
#define I_DIM 1024

// ---------------- scratch (static device globals; allocation-free) ----------------
__device__ float g_xnorm[T_TOK * D_DIM];
__device__ float g_q[T_TOK * N_H * HD];
__device__ float g_k[T_TOK * N_KVH * HD];
__device__ float g_v[T_TOK * N_KVH * HD];
__device__ float g_attn[T_TOK * N_H * HD];
__device__ float g_x2[T_TOK * D_DIM];
__device__ float g_gbuf[N_E * T_TOK * I_DIM];
__device__ float g_ubuf[N_E * T_TOK * I_DIM];
__device__ int   g_cnt[N_E];
__device__ int   g_tok[N_E * T_TOK];
__device__ float g_wt[N_E * T_TOK];
__device__ float g_cos[T_TOK * 64];
__device__ float g_sin[T_TOK * 64];

// ---------------- RMSNorm ----------------
__global__ void rmsnorm_kernel(const float* __restrict__ x, const float* __restrict__ w,
                               float* __restrict__ out) {
    int row = blockIdx.x, tid = threadIdx.x;
    const float4* xr = (const float4*)(x + (size_t)row * D_DIM);
    const float4* wr = (const float4*)w;
    float ss = 0.f;
#pragma unroll
    for (int p = 0; p < 2; ++p) {
        float4 v = xr[tid + p * 256];
        ss += v.x * v.x + v.y * v.y + v.z * v.z + v.w * v.w;
    }
#pragma unroll
    for (int o = 16; o; o >>= 1) ss += __shfl_xor_sync(0xffffffffu, ss, o);
    __shared__ float red[8];
    if ((tid & 31) == 0) red[tid >> 5] = ss;
    __syncthreads();
    float tot = 0.f;
#pragma unroll
    for (int i = 0; i < 8; ++i) tot += red[i];
    float inv = rsqrtf(tot * (1.0f / D_DIM) + 1e-6f);
    float4* o4 = (float4*)(out + (size_t)row * D_DIM);
#pragma unroll
    for (int p = 0; p < 2; ++p) {
        int i = tid + p * 256;
        float4 v = xr[i], wv = wr[i];
        o4[i] = make_float4(v.x * inv * wv.x, v.y * inv * wv.y,
                            v.z * inv * wv.z, v.w * inv * wv.w);
    }
}

// ---------------- TF32x3 tensor-core GEMM ----------------
__device__ __forceinline__ void split_tf32(float x, uint32_t& hi, uint32_t& lo) {
    asm("cvt.rna.tf32.f32 %0, %1;" : "=r"(hi) : "f"(x));
    float lof = x - __uint_as_float(hi);
    asm("cvt.rna.tf32.f32 %0, %1;" : "=r"(lo) : "f"(lof));
}

#define MMA_TF32(c0, c1, c2, c3, a0, a1, a2, a3, b0, b1)                         \
    asm volatile(                                                                \
        "mma.sync.aligned.m16n8k8.row.col.f32.tf32.tf32.f32 "                    \
        "{%0,%1,%2,%3}, {%4,%5,%6,%7}, {%8,%9}, {%0,%1,%2,%3};\n"                \
        : "+f"(c0), "+f"(c1), "+f"(c2), "+f"(c3)                                 \
        : "r"(a0), "r"(a1), "r"(a2), "r"(a3), "r"(b0), "r"(b1))

// EPI: 0 = +bias store, 1 = +residual store, 2 = plain store, 3 = atomic scatter *weight
// GATHER: A rows indexed through token list. DUAL: blockIdx.z low bit selects B/C/bias set.
template <int EPI, bool GATHER, bool DUAL>
__global__ void __launch_bounds__(256)
tgemm_kernel(const float* __restrict__ A, const float* __restrict__ B, float* __restrict__ C,
             int M, int N, int Kd,
             const float* __restrict__ bias, const float* __restrict__ res,
             const int* __restrict__ cnt, const int* __restrict__ tok,
             const float* __restrict__ wt,
             long aBatch, long bBatch, long cBatch,
             const float* __restrict__ B2, float* __restrict__ C2,
             const float* __restrict__ bias2) {
    __shared__ float As[16 * 136];   // [k][m], padded
    __shared__ float Bs[16 * 136];   // [k][n], padded
    const int zz = blockIdx.z;
    const int e = DUAL ? (zz >> 1) : zz;
    const int half = DUAL ? (zz & 1) : 0;
    const int Mcur = cnt ? cnt[e] : M;
    const int m0 = blockIdx.y * 128;
    if (m0 >= Mcur) return;
    const int n0 = blockIdx.x * 128;
    const float* Bsel = (DUAL && half) ? B2 : B;
    float* Csel = (DUAL && half) ? C2 : C;
    const float* biassel = (DUAL && half) ? bias2 : bias;
    const float* Ab = A + (size_t)e * aBatch;
    const float* Bb = Bsel + (size_t)e * bBatch;
    float* Cb = Csel + (size_t)e * cBatch;
    const int* tokb = tok ? tok + e * T_TOK : nullptr;
    const int tid = threadIdx.x;
    const int lane = tid & 31, warp = tid >> 5;
    const int warp_m = (warp >> 2) * 64, warp_n = (warp & 3) * 32;
    const int gr = lane >> 2, gc = lane & 3;

    // A-load indexing
    const int lr0 = tid >> 2;
    const int lc4 = (tid & 3) << 2;
    int arow[2];
    bool av[2];
#pragma unroll
    for (int p = 0; p < 2; ++p) {
        int rg = m0 + lr0 + p * 64;
        av[p] = rg < Mcur;
        arow[p] = av[p] ? (GATHER ? tokb[rg] : rg) : 0;
    }

    float acc[4][4][4];
#pragma unroll
    for (int mt = 0; mt < 4; ++mt)
#pragma unroll
        for (int nt = 0; nt < 4; ++nt)
#pragma unroll
            for (int r = 0; r < 4; ++r) acc[mt][nt][r] = 0.f;

    for (int kk = 0; kk < Kd; kk += 16) {
#pragma unroll
        for (int p = 0; p < 2; ++p) {
            float4 va = make_float4(0.f, 0.f, 0.f, 0.f);
            if (av[p]) va = *(const float4*)(Ab + (size_t)arow[p] * Kd + kk + lc4);
            int r = lr0 + p * 64;
            As[(lc4 + 0) * 136 + r] = va.x;
            As[(lc4 + 1) * 136 + r] = va.y;
            As[(lc4 + 2) * 136 + r] = va.z;
            As[(lc4 + 3) * 136 + r] = va.w;
        }
#pragma unroll
        for (int p = 0; p < 2; ++p) {
            int idx = tid + p * 256;
            int r = idx >> 5, c4 = (idx & 31) << 2;
            *(float4*)&Bs[r * 136 + c4] = *(const float4*)(Bb + (size_t)(kk + r) * N + n0 + c4);
        }
        __syncthreads();
#pragma unroll
        for (int sub = 0; sub < 2; ++sub) {
            const int k8 = sub * 8;
            uint32_t ahi[4][4], alo[4][4];
#pragma unroll
            for (int mt = 0; mt < 4; ++mt) {
                int rowb = warp_m + mt * 16 + gr;
#pragma unroll
                for (int j = 0; j < 4; ++j) {
                    int kidx = k8 + gc + ((j >> 1) << 2);
                    int midx = rowb + ((j & 1) << 3);
                    split_tf32(As[kidx * 136 + midx], ahi[mt][j], alo[mt][j]);
                }
            }
            uint32_t bhi[4][2], blo[4][2];
#pragma unroll
            for (int nt = 0; nt < 4; ++nt) {
                int nidx = warp_n + nt * 8 + gr;
#pragma unroll
                for (int j = 0; j < 2; ++j) {
                    int kidx = k8 + gc + (j << 2);
                    split_tf32(Bs[kidx * 136 + nidx], bhi[nt][j], blo[nt][j]);
                }
            }
#pragma unroll
            for (int mt = 0; mt < 4; ++mt)
#pragma unroll
                for (int nt = 0; nt < 4; ++nt) {
                    float* c = acc[mt][nt];
                    MMA_TF32(c[0], c[1], c[2], c[3],
                             ahi[mt][0], ahi[mt][1], ahi[mt][2], ahi[mt][3],
                             blo[nt][0], blo[nt][1]);
                    MMA_TF32(c[0], c[1], c[2], c[3],
                             alo[mt][0], alo[mt][1], alo[mt][2], alo[mt][3],
                             bhi[nt][0], bhi[nt][1]);
                    MMA_TF32(c[0], c[1], c[2], c[3],
                             ahi[mt][0], ahi[mt][1], ahi[mt][2], ahi[mt][3],
                             bhi[nt][0], bhi[nt][1]);
                }
        }
        __syncthreads();
    }

    // epilogue: acc[mt][nt] regs map to rows (r0, r0+8), cols (c0, c0+1)
#pragma unroll
    for (int mt = 0; mt < 4; ++mt) {
#pragma unroll
        for (int rr = 0; rr < 2; ++rr) {
            int rg = m0 + warp_m + mt * 16 + gr + rr * 8;
            if (rg >= Mcur) continue;
            if (EPI == 3) {
                int t = tokb[rg];
                float w = wt[e * T_TOK + rg];
                float* outr = C + (size_t)t * N;
#pragma unroll
                for (int nt = 0; nt < 4; ++nt) {
                    int cb = n0 + warp_n + nt * 8 + gc * 2;
                    atomicAdd(&outr[cb], acc[mt][nt][rr * 2] * w);
                    atomicAdd(&outr[cb + 1], acc[mt][nt][rr * 2 + 1] * w);
                }
            } else {
#pragma unroll
                for (int nt = 0; nt < 4; ++nt) {
                    int cb = n0 + warp_n + nt * 8 + gc * 2;
                    float v0 = acc[mt][nt][rr * 2], v1 = acc[mt][nt][rr * 2 + 1];
                    if (EPI == 0) { v0 += biassel[cb]; v1 += biassel[cb + 1]; }
                    if (EPI == 1) {
                        const float* rrow = res + (size_t)rg * N;
                        v0 += rrow[cb]; v1 += rrow[cb + 1];
                    }
                    *(float2*)(Cb + (size_t)rg * N + cb) = make_float2(v0, v1);
                }
            }
        }
    }
}

// ---------------- RoPE: accurate table (double trig) + f32 apply ----------------
__global__ void rope_table_kernel(const int* __restrict__ pos,
                                  float* __restrict__ ctab, float* __restrict__ stab) {
    int t = blockIdx.x, i = threadIdx.x;  // 64 threads
    float p = (float)pos[t];
    float invf = (float)exp(-(double)i * (13.815510557964274 / 64.0));
    float fr = p * invf;
    double cd = cos((double)fr), sd = sin((double)fr);
    ctab[t * 64 + i] = (float)cd;
    stab[t * 64 + i] = (float)sd;
}

__global__ void rope_apply_kernel(float* __restrict__ x, const float* __restrict__ ctab,
                                  const float* __restrict__ stab, int nheads) {
    int t = blockIdx.x, h = blockIdx.y, i = threadIdx.x;  // 64 threads
    float c = ctab[t * 64 + i], s = stab[t * 64 + i];
    float* b = x + ((size_t)t * nheads + h) * HD;
    float x1 = b[i], x2 = b[i + 64];
    b[i] = x1 * c - x2 * s;
    b[i + 64] = x2 * c + x1 * s;
}

// ---------------- flash attention v2 (validated) ----------------
#define F2_QSTR 129
#define F2_SSTR 65
__global__ void __launch_bounds__(256)
flash2_kernel(const float* __restrict__ q, const float* __restrict__ k,
              const float* __restrict__ v, float* __restrict__ o) {
    extern __shared__ float sm2[];
    float* Qs = sm2;
    float* Ks = sm2 + 64 * F2_QSTR;
    float* Ss = sm2 + 2 * 64 * F2_QSTR;
    const int tid = threadIdx.x;
    const int r = tid >> 2;
    const int g = tid & 3;
    const int qt = blockIdx.x, head = blockIdx.y, kvh = head >> 2;
    const int qr0 = qt * 64;
    const float scale = 0.08838834764831845f;

    for (int it = tid; it < 2048; it += 256) {
        int rr = it >> 5, c4 = (it & 31) << 2;
        float4 vq = *(const float4*)(q + (size_t)(qr0 + rr) * (N_H * HD) + head * HD + c4);
        float* dst = Qs + rr * F2_QSTR + c4;
        dst[0] = vq.x; dst[1] = vq.y; dst[2] = vq.z; dst[3] = vq.w;
    }
    float oacc[32];
#pragma unroll
    for (int c = 0; c < 32; ++c) oacc[c] = 0.f;
    float mrow = -INFINITY, lrow = 0.f;
    __syncthreads();

    for (int kt = 0; kt <= qt; ++kt) {
        const int kr0 = kt * 64;
        for (int it = tid; it < 2048; it += 256) {
            int rr = it >> 5, c4 = (it & 31) << 2;
            float4 vk = *(const float4*)(k + (size_t)(kr0 + rr) * (N_KVH * HD) + kvh * HD + c4);
            float* dst = Ks + rr * F2_QSTR + c4;
            dst[0] = vk.x; dst[1] = vk.y; dst[2] = vk.z; dst[3] = vk.w;
        }
        __syncthreads();
        float s[16];
#pragma unroll
        for (int jj = 0; jj < 16; ++jj) s[jj] = 0.f;
        for (int d = 0; d < 128; ++d) {
            float qv = Qs[r * F2_QSTR + d];
#pragma unroll
            for (int jj = 0; jj < 16; ++jj)
                s[jj] = fmaf(qv, Ks[(g * 16 + jj) * F2_QSTR + d], s[jj]);
        }
        float mx = -INFINITY;
#pragma unroll
        for (int jj = 0; jj < 16; ++jj) {
            int col = kr0 + g * 16 + jj;
            float sv = (col <= qr0 + r) ? s[jj] * scale : -INFINITY;
            s[jj] = sv;
            mx = fmaxf(mx, sv);
        }
        mx = fmaxf(mx, __shfl_xor_sync(0xffffffffu, mx, 1));
        mx = fmaxf(mx, __shfl_xor_sync(0xffffffffu, mx, 2));
        float nm = fmaxf(mrow, mx);
        float rs = 0.f;
#pragma unroll
        for (int jj = 0; jj < 16; ++jj) {
            float pv = expf(s[jj] - nm);
            s[jj] = pv;
            rs += pv;
        }
        rs += __shfl_xor_sync(0xffffffffu, rs, 1);
        rs += __shfl_xor_sync(0xffffffffu, rs, 2);
        float alpha = expf(mrow - nm);
        lrow = lrow * alpha + rs;
        mrow = nm;
#pragma unroll
        for (int jj = 0; jj < 16; ++jj) Ss[r * F2_SSTR + g * 16 + jj] = s[jj];
#pragma unroll
        for (int c = 0; c < 32; ++c) oacc[c] *= alpha;
        __syncthreads();
        for (int it = tid; it < 2048; it += 256) {
            int rr = it >> 5, c4 = (it & 31) << 2;
            float4 vv = *(const float4*)(v + (size_t)(kr0 + rr) * (N_KVH * HD) + kvh * HD + c4);
            float* dst = Ks + rr * F2_QSTR + c4;
            dst[0] = vv.x; dst[1] = vv.y; dst[2] = vv.z; dst[3] = vv.w;
        }
        __syncthreads();
        for (int j = 0; j < 64; ++j) {
            float pv = Ss[r * F2_SSTR + j];
            const float* vrow = Ks + j * F2_QSTR + g * 32;
#pragma unroll
            for (int cc = 0; cc < 32; ++cc) {
                int c = (cc + g * 8) & 31;
                oacc[cc] = fmaf(pv, vrow[c], oacc[cc]);
            }
        }
        __syncthreads();
    }
    float invl = 1.f / lrow;
    float* orow = o + (size_t)(qr0 + r) * (N_H * HD) + head * HD + g * 32;
#pragma unroll
    for (int cc = 0; cc < 32; ++cc) {
        int c = (cc + g * 8) & 31;
        orow[c] = oacc[cc] * invl;
    }
}

// ---------------- router: logits -> softmax -> top2 -> scatter ----------------
__global__ void router_kernel(const float* __restrict__ x, const float* __restrict__ gw,
                              int* __restrict__ cnt, int* __restrict__ tok,
                              float* __restrict__ wt) {
    int t = blockIdx.x;
    const float* xr = x + (size_t)t * D_DIM;
    float acc[8] = {0, 0, 0, 0, 0, 0, 0, 0};
    for (int d = threadIdx.x; d < D_DIM; d += 256) {
        float xv = xr[d];
        const float4* g4 = (const float4*)(gw + (size_t)d * N_E);
        float4 a = g4[0], b = g4[1];
        acc[0] = fmaf(xv, a.x, acc[0]); acc[1] = fmaf(xv, a.y, acc[1]);
        acc[2] = fmaf(xv, a.z, acc[2]); acc[3] = fmaf(xv, a.w, acc[3]);
        acc[4] = fmaf(xv, b.x, acc[4]); acc[5] = fmaf(xv, b.y, acc[5]);
        acc[6] = fmaf(xv, b.z, acc[6]); acc[7] = fmaf(xv, b.w, acc[7]);
    }
    __shared__ float smr[8][256];
#pragma unroll
    for (int e = 0; e < 8; ++e) smr[e][threadIdx.x] = acc[e];
    __syncthreads();
    for (int s = 128; s; s >>= 1) {
        if (threadIdx.x < s)
#pragma unroll
            for (int e = 0; e < 8; ++e) smr[e][threadIdx.x] += smr[e][threadIdx.x + s];
        __syncthreads();
    }
    if (threadIdx.x == 0) {
        float l[8], p[8];
        float mx = -1e30f;
#pragma unroll
        for (int e = 0; e < 8; ++e) { l[e] = smr[e][0]; mx = fmaxf(mx, l[e]); }
        float ssum = 0.f;
#pragma unroll
        for (int e = 0; e < 8; ++e) { p[e] = expf(l[e] - mx); ssum += p[e]; }
#pragma unroll
        for (int e = 0; e < 8; ++e) p[e] /= ssum;
        int i0 = 0; float p0 = p[0];
#pragma unroll
        for (int e = 1; e < 8; ++e) if (p[e] > p0) { p0 = p[e]; i0 = e; }
        int i1 = -1; float p1 = -1.f;
#pragma unroll
        for (int e = 0; e < 8; ++e) if (e != i0 && p[e] > p1) { p1 = p[e]; i1 = e; }
        float wn = p0 + p1;
        int pos = atomicAdd(&cnt[i0], 1);
        tok[i0 * T_TOK + pos] = t; wt[i0 * T_TOK + pos] = p0 / wn;
        pos = atomicAdd(&cnt[i1], 1);
        tok[i1 * T_TOK + pos] = t; wt[i1 * T_TOK + pos] = p1 / wn;
    }
}

// ---------------- silu(g)*u, only over active rows per expert ----------------
__global__ void silu_mul_kernel(float* __restrict__ g, const float* __restrict__ u,
                                const int* __restrict__ cnt) {
    int e = blockIdx.z;
    int row = blockIdx.y;
    if (row >= cnt[e]) return;
    size_t base = ((size_t)e * T_TOK + row) * I_DIM;
    int i = blockIdx.x * 256 + threadIdx.x;
    float4 gv = ((const float4*)(g + base))[i];
    float4 uv = ((const float4*)(u + base))[i];
    gv.x = gv.x / (1.f + __expf(-gv.x)) * uv.x;
    gv.y = gv.y / (1.f + __expf(-gv.y)) * uv.y;
    gv.z = gv.z / (1.f + __expf(-gv.z)) * uv.z;
    gv.w = gv.w / (1.f + __expf(-gv.w)) * uv.w;
    ((float4*)(g + base))[i] = gv;
}

// ---------------- launch ----------------
extern "C" void kernel_launch(void* const* d_in, const int* in_sizes, int n_in,
                              void* d_out, int out_size) {
    const float* hidden = (const float*)d_in[0];
    const int* positions = (const int*)d_in[1];
    const float* ln1 = (const float*)d_in[2];
    const float* ln2 = (const float*)d_in[3];
    const float* wq = (const float*)d_in[4];
    const float* bq = (const float*)d_in[5];
    const float* wk = (const float*)d_in[6];
    const float* bk = (const float*)d_in[7];
    const float* wv = (const float*)d_in[8];
    const float* bv = (const float*)d_in[9];
    const float* wo = (const float*)d_in[10];
    const float* gate_w = (const float*)d_in[11];
    const float* w_gate = (const float*)d_in[12];
    const float* w_up = (const float*)d_in[13];
    const float* w_down = (const float*)d_in[14];
    float* out = (float*)d_out;

    float *xnorm, *q, *k, *v, *attn, *x2, *gbuf, *ubuf, *wt, *ctab, *stab;
    int *cnt, *tok;
    cudaGetSymbolAddress((void**)&xnorm, g_xnorm);
    cudaGetSymbolAddress((void**)&q, g_q);
    cudaGetSymbolAddress((void**)&k, g_k);
    cudaGetSymbolAddress((void**)&v, g_v);
    cudaGetSymbolAddress((void**)&attn, g_attn);
    cudaGetSymbolAddress((void**)&x2, g_x2);
    cudaGetSymbolAddress((void**)&gbuf, g_gbuf);
    cudaGetSymbolAddress((void**)&ubuf, g_ubuf);
    cudaGetSymbolAddress((void**)&cnt, g_cnt);
    cudaGetSymbolAddress((void**)&tok, g_tok);
    cudaGetSymbolAddress((void**)&wt, g_wt);
    cudaGetSymbolAddress((void**)&ctab, g_cos);
    cudaGetSymbolAddress((void**)&stab, g_sin);

    const int smem_flash = (2 * 64 * F2_QSTR + 64 * F2_SSTR) * sizeof(float);
    cudaFuncSetAttribute(flash2_kernel, cudaFuncAttributeMaxDynamicSharedMemorySize, smem_flash);

    // 0) RoPE table (accurate trig)
    rope_table_kernel<<<T_TOK, 64>>>(positions, ctab, stab);
    // 1) RMSNorm 1
    rmsnorm_kernel<<<T_TOK, 256>>>(hidden, ln1, xnorm);
    // 2) Q projection (+bias); K+V fused via DUAL
    tgemm_kernel<0, false, false><<<dim3(16, 16, 1), 256>>>(
        xnorm, wq, q, T_TOK, 2048, 2048, bq, nullptr, nullptr, nullptr, nullptr,
        0, 0, 0, nullptr, nullptr, nullptr);
    tgemm_kernel<0, false, true><<<dim3(4, 16, 2), 256>>>(
        xnorm, wk, k, T_TOK, 512, 2048, bk, nullptr, nullptr, nullptr, nullptr,
        0, 0, 0, wv, v, bv);
    // 3) RoPE apply
    rope_apply_kernel<<<dim3(T_TOK, N_H), 64>>>(q, ctab, stab, N_H);
    rope_apply_kernel<<<dim3(T_TOK, N_KVH), 64>>>(k, ctab, stab, N_KVH);
    // 4) attention
    flash2_kernel<<<dim3(T_TOK / 64, N_H), 256, smem_flash>>>(q, k, v, attn);
    // 5) output proj + residual -> d_out holds h
    tgemm_kernel<1, false, false><<<dim3(16, 16, 1), 256>>>(
        attn, wo, out, T_TOK, 2048, 2048, nullptr, hidden, nullptr, nullptr, nullptr,
        0, 0, 0, nullptr, nullptr, nullptr);
    // 6) RMSNorm 2
    rmsnorm_kernel<<<T_TOK, 256>>>(out, ln2, x2);
    // 7) router
    cudaMemsetAsync(cnt, 0, N_E * sizeof(int));
    router_kernel<<<T_TOK, 256>>>(x2, gate_w, cnt, tok, wt);
    // 8) expert gate+up fused via DUAL (gathered rows, early-exit on count)
    tgemm_kernel<2, true, true><<<dim3(I_DIM / 128, T_TOK / 128, N_E * 2), 256>>>(
        x2, w_gate, gbuf, 0, I_DIM, D_DIM, nullptr, nullptr, cnt, tok, nullptr,
        0, (long)D_DIM * I_DIM, (long)T_TOK * I_DIM, w_up, ubuf, nullptr);
    // 9) silu(g)*u on active rows only
    silu_mul_kernel<<<dim3(1, T_TOK, N_E), 256>>>(gbuf, ubuf, cnt);
    // 10) expert down GEMM, scatter *weight into d_out (residual already there)
    tgemm_kernel<3, false, false><<<dim3(D_DIM / 128, T_TOK / 128, N_E), 256>>>(
        gbuf, w_down, out, 0, D_DIM, I_DIM, nullptr, nullptr, cnt, tok, wt,
        (long)T_TOK * I_DIM, (long)I_DIM * D_DIM, 0, nullptr, nullptr, nullptr);
}

// round 7
// speedup vs baseline: 14.4272x; 1.4842x over previous
#include <cuda_runtime.h>
#include <cuda_bf16.h>
#include <math.h>
#include <stdint.h>

#define T_TOK 2048
#define D_DIM 2048
#define N_H   16
#define N_KVH 4
#define HD    128
#define N_E   8
#define I_DIM 1024

// ---------------- scratch (static device globals; allocation-free) ----------------
__device__ float g_xnorm[T_TOK * D_DIM];
__device__ float g_q[T_TOK * N_H * HD];
__device__ float g_k[T_TOK * N_KVH * HD];
__device__ float g_v[T_TOK * N_KVH * HD];
__device__ float g_attn[T_TOK * N_H * HD];
__device__ float g_x2[T_TOK * D_DIM];
__device__ float g_gbuf[N_E * T_TOK * I_DIM];
__device__ float g_ubuf[N_E * T_TOK * I_DIM];
__device__ int   g_cnt[N_E];
__device__ int   g_tok[N_E * T_TOK];
__device__ float g_wt[N_E * T_TOK];
__device__ float g_cos[T_TOK * 64];
__device__ float g_sin[T_TOK * 64];

// ---------------- tf32 helpers ----------------
__device__ __forceinline__ void split_tf32(float x, uint32_t& hi, uint32_t& lo) {
    asm("cvt.rna.tf32.f32 %0, %1;" : "=r"(hi) : "f"(x));
    float lof = x - __uint_as_float(hi);
    asm("cvt.rna.tf32.f32 %0, %1;" : "=r"(lo) : "f"(lof));
}

#define MMA_TF32(c0, c1, c2, c3, a0, a1, a2, a3, b0, b1)                         \
    asm volatile(                                                                \
        "mma.sync.aligned.m16n8k8.row.col.f32.tf32.tf32.f32 "                    \
        "{%0,%1,%2,%3}, {%4,%5,%6,%7}, {%8,%9}, {%0,%1,%2,%3};\n"                \
        : "+f"(c0), "+f"(c1), "+f"(c2), "+f"(c3)                                 \
        : "r"(a0), "r"(a1), "r"(a2), "r"(a3), "r"(b0), "r"(b1))

// ---------------- RMSNorm ----------------
__global__ void rmsnorm_kernel(const float* __restrict__ x, const float* __restrict__ w,
                               float* __restrict__ out) {
    int row = blockIdx.x, tid = threadIdx.x;
    const float4* xr = (const float4*)(x + (size_t)row * D_DIM);
    const float4* wr = (const float4*)w;
    float ss = 0.f;
#pragma unroll
    for (int p = 0; p < 2; ++p) {
        float4 v = xr[tid + p * 256];
        ss += v.x * v.x + v.y * v.y + v.z * v.z + v.w * v.w;
    }
#pragma unroll
    for (int o = 16; o; o >>= 1) ss += __shfl_xor_sync(0xffffffffu, ss, o);
    __shared__ float red[8];
    if ((tid & 31) == 0) red[tid >> 5] = ss;
    __syncthreads();
    float tot = 0.f;
#pragma unroll
    for (int i = 0; i < 8; ++i) tot += red[i];
    float inv = rsqrtf(tot * (1.0f / D_DIM) + 1e-6f);
    float4* o4 = (float4*)(out + (size_t)row * D_DIM);
#pragma unroll
    for (int p = 0; p < 2; ++p) {
        int i = tid + p * 256;
        float4 v = xr[i], wv = wr[i];
        o4[i] = make_float4(v.x * inv * wv.x, v.y * inv * wv.y,
                            v.z * inv * wv.z, v.w * inv * wv.w);
    }
}

// ---------------- TF32x3 tensor-core GEMM (pre-split smem) ----------------
// EPI: 0 = +bias store, 1 = +residual store, 2 = plain store, 3 = atomic scatter *weight
template <int EPI, bool GATHER, bool DUAL>
__global__ void __launch_bounds__(256)
tgemm_kernel(const float* __restrict__ A, const float* __restrict__ B, float* __restrict__ C,
             int M, int N, int Kd,
             const float* __restrict__ bias, const float* __restrict__ res,
             const int* __restrict__ cnt, const int* __restrict__ tok,
             const float* __restrict__ wt,
             long aBatch, long bBatch, long cBatch,
             const float* __restrict__ B2, float* __restrict__ C2,
             const float* __restrict__ bias2) {
    __shared__ float Ah[16 * 136], Al[16 * 136];   // [k][m]
    __shared__ float Bh[16 * 136], Bl[16 * 136];   // [k][n]
    const int zz = blockIdx.z;
    const int e = DUAL ? (zz >> 1) : zz;
    const int half = DUAL ? (zz & 1) : 0;
    const int Mcur = cnt ? cnt[e] : M;
    const int m0 = blockIdx.y * 128;
    if (m0 >= Mcur) return;
    const int n0 = blockIdx.x * 128;
    const float* Bsel = (DUAL && half) ? B2 : B;
    float* Csel = (DUAL && half) ? C2 : C;
    const float* biassel = (DUAL && half) ? bias2 : bias;
    const float* Ab = A + (size_t)e * aBatch;
    const float* Bb = Bsel + (size_t)e * bBatch;
    float* Cb = Csel + (size_t)e * cBatch;
    const int* tokb = tok ? tok + e * T_TOK : nullptr;
    const int tid = threadIdx.x;
    const int lane = tid & 31, warp = tid >> 5;
    const int warp_m = (warp >> 2) * 64, warp_n = (warp & 3) * 32;
    const int gr = lane >> 2, gc = lane & 3;

    const int lr0 = tid >> 2;
    const int lc4 = (tid & 3) << 2;
    int arow[2];
    bool av[2];
#pragma unroll
    for (int p = 0; p < 2; ++p) {
        int rg = m0 + lr0 + p * 64;
        av[p] = rg < Mcur;
        arow[p] = av[p] ? (GATHER ? tokb[rg] : rg) : 0;
    }

    float acc[4][4][4];
#pragma unroll
    for (int mt = 0; mt < 4; ++mt)
#pragma unroll
        for (int nt = 0; nt < 4; ++nt)
#pragma unroll
            for (int r = 0; r < 4; ++r) acc[mt][nt][r] = 0.f;

    for (int kk = 0; kk < Kd; kk += 16) {
#pragma unroll
        for (int p = 0; p < 2; ++p) {
            float4 va = make_float4(0.f, 0.f, 0.f, 0.f);
            if (av[p]) va = *(const float4*)(Ab + (size_t)arow[p] * Kd + kk + lc4);
            int r = lr0 + p * 64;
            uint32_t h, l;
            split_tf32(va.x, h, l);
            Ah[(lc4 + 0) * 136 + r] = __uint_as_float(h); Al[(lc4 + 0) * 136 + r] = __uint_as_float(l);
            split_tf32(va.y, h, l);
            Ah[(lc4 + 1) * 136 + r] = __uint_as_float(h); Al[(lc4 + 1) * 136 + r] = __uint_as_float(l);
            split_tf32(va.z, h, l);
            Ah[(lc4 + 2) * 136 + r] = __uint_as_float(h); Al[(lc4 + 2) * 136 + r] = __uint_as_float(l);
            split_tf32(va.w, h, l);
            Ah[(lc4 + 3) * 136 + r] = __uint_as_float(h); Al[(lc4 + 3) * 136 + r] = __uint_as_float(l);
        }
#pragma unroll
        for (int p = 0; p < 2; ++p) {
            int idx = tid + p * 256;
            int r = idx >> 5, c4 = (idx & 31) << 2;
            float4 vb = *(const float4*)(Bb + (size_t)(kk + r) * N + n0 + c4);
            uint32_t h, l;
            split_tf32(vb.x, h, l);
            Bh[r * 136 + c4 + 0] = __uint_as_float(h); Bl[r * 136 + c4 + 0] = __uint_as_float(l);
            split_tf32(vb.y, h, l);
            Bh[r * 136 + c4 + 1] = __uint_as_float(h); Bl[r * 136 + c4 + 1] = __uint_as_float(l);
            split_tf32(vb.z, h, l);
            Bh[r * 136 + c4 + 2] = __uint_as_float(h); Bl[r * 136 + c4 + 2] = __uint_as_float(l);
            split_tf32(vb.w, h, l);
            Bh[r * 136 + c4 + 3] = __uint_as_float(h); Bl[r * 136 + c4 + 3] = __uint_as_float(l);
        }
        __syncthreads();
#pragma unroll
        for (int sub = 0; sub < 2; ++sub) {
            const int k8 = sub * 8;
            uint32_t ahi[4][4], alo[4][4];
#pragma unroll
            for (int mt = 0; mt < 4; ++mt) {
                int rowb = warp_m + mt * 16 + gr;
#pragma unroll
                for (int j = 0; j < 4; ++j) {
                    int kidx = k8 + gc + ((j >> 1) << 2);
                    int midx = rowb + ((j & 1) << 3);
                    ahi[mt][j] = __float_as_uint(Ah[kidx * 136 + midx]);
                    alo[mt][j] = __float_as_uint(Al[kidx * 136 + midx]);
                }
            }
            uint32_t bhi[4][2], blo[4][2];
#pragma unroll
            for (int nt = 0; nt < 4; ++nt) {
                int nidx = warp_n + nt * 8 + gr;
#pragma unroll
                for (int j = 0; j < 2; ++j) {
                    int kidx = k8 + gc + (j << 2);
                    bhi[nt][j] = __float_as_uint(Bh[kidx * 136 + nidx]);
                    blo[nt][j] = __float_as_uint(Bl[kidx * 136 + nidx]);
                }
            }
#pragma unroll
            for (int mt = 0; mt < 4; ++mt)
#pragma unroll
                for (int nt = 0; nt < 4; ++nt) {
                    float* c = acc[mt][nt];
                    MMA_TF32(c[0], c[1], c[2], c[3],
                             ahi[mt][0], ahi[mt][1], ahi[mt][2], ahi[mt][3],
                             blo[nt][0], blo[nt][1]);
                    MMA_TF32(c[0], c[1], c[2], c[3],
                             alo[mt][0], alo[mt][1], alo[mt][2], alo[mt][3],
                             bhi[nt][0], bhi[nt][1]);
                    MMA_TF32(c[0], c[1], c[2], c[3],
                             ahi[mt][0], ahi[mt][1], ahi[mt][2], ahi[mt][3],
                             bhi[nt][0], bhi[nt][1]);
                }
        }
        __syncthreads();
    }

#pragma unroll
    for (int mt = 0; mt < 4; ++mt) {
#pragma unroll
        for (int rr = 0; rr < 2; ++rr) {
            int rg = m0 + warp_m + mt * 16 + gr + rr * 8;
            if (rg >= Mcur) continue;
            if (EPI == 3) {
                int t = tokb[rg];
                float w = wt[e * T_TOK + rg];
                float* outr = C + (size_t)t * N;
#pragma unroll
                for (int nt = 0; nt < 4; ++nt) {
                    int cb = n0 + warp_n + nt * 8 + gc * 2;
                    atomicAdd(&outr[cb], acc[mt][nt][rr * 2] * w);
                    atomicAdd(&outr[cb + 1], acc[mt][nt][rr * 2 + 1] * w);
                }
            } else {
#pragma unroll
                for (int nt = 0; nt < 4; ++nt) {
                    int cb = n0 + warp_n + nt * 8 + gc * 2;
                    float v0 = acc[mt][nt][rr * 2], v1 = acc[mt][nt][rr * 2 + 1];
                    if (EPI == 0) { v0 += biassel[cb]; v1 += biassel[cb + 1]; }
                    if (EPI == 1) {
                        const float* rrow = res + (size_t)rg * N;
                        v0 += rrow[cb]; v1 += rrow[cb + 1];
                    }
                    *(float2*)(Cb + (size_t)rg * N + cb) = make_float2(v0, v1);
                }
            }
        }
    }
}

// ---------------- RoPE: accurate table (double trig) + f32 apply ----------------
__global__ void rope_table_kernel(const int* __restrict__ pos,
                                  float* __restrict__ ctab, float* __restrict__ stab) {
    int t = blockIdx.x, i = threadIdx.x;  // 64 threads
    float p = (float)pos[t];
    float invf = (float)exp(-(double)i * (13.815510557964274 / 64.0));
    float fr = p * invf;
    double cd = cos((double)fr), sd = sin((double)fr);
    ctab[t * 64 + i] = (float)cd;
    stab[t * 64 + i] = (float)sd;
}

__global__ void rope_apply_kernel(float* __restrict__ x, const float* __restrict__ ctab,
                                  const float* __restrict__ stab, int nheads) {
    int t = blockIdx.x, h = blockIdx.y, i = threadIdx.x;  // 64 threads
    float c = ctab[t * 64 + i], s = stab[t * 64 + i];
    float* b = x + ((size_t)t * nheads + h) * HD;
    float x1 = b[i], x2 = b[i + 64];
    b[i] = x1 * c - x2 * s;
    b[i + 64] = x2 * c + x1 * s;
}

// ---------------- flash attention v3: tf32x3 tensor cores, validated softmax ----------------
#define QST 132
#define PST 68
__global__ void __launch_bounds__(256)
flash3_kernel(const float* __restrict__ q, const float* __restrict__ k,
              const float* __restrict__ v, float* __restrict__ o) {
    extern __shared__ float sm3[];
    float* Qhi = sm3;                    // 64*132
    float* Qlo = Qhi + 64 * QST;
    float* KVhi = Qlo + 64 * QST;        // K then V
    float* KVlo = KVhi + 64 * QST;
    float* Phi = KVlo + 64 * QST;        // 64*68 (S scratch, then P hi)
    float* Plo = Phi + 64 * PST;
    float* salpha = Plo + 64 * PST;      // 64
    const int tid = threadIdx.x;
    const int lane = tid & 31, warp = tid >> 5;
    const int gr = lane >> 2, gc = lane & 3;
    const int wms = (warp >> 1) * 16;          // S/O warp row base
    const int wns = (warp & 1) * 32;           // S warp col base
    const int wno = (warp & 1) * 64;           // O warp col base
    const int sr = tid >> 2, sg = tid & 3;     // softmax role: row sr, col group sg
    const int qt = blockIdx.x, head = blockIdx.y, kvh = head >> 2;
    const int qr0 = qt * 64;
    const float scale = 0.08838834764831845f;

    // stage Q, pre-split (reused across all kt)
    for (int it = tid; it < 2048; it += 256) {
        int rr = it >> 5, c4 = (it & 31) << 2;
        float4 vq = *(const float4*)(q + (size_t)(qr0 + rr) * (N_H * HD) + head * HD + c4);
        uint32_t h, l;
        split_tf32(vq.x, h, l); Qhi[rr * QST + c4 + 0] = __uint_as_float(h); Qlo[rr * QST + c4 + 0] = __uint_as_float(l);
        split_tf32(vq.y, h, l); Qhi[rr * QST + c4 + 1] = __uint_as_float(h); Qlo[rr * QST + c4 + 1] = __uint_as_float(l);
        split_tf32(vq.z, h, l); Qhi[rr * QST + c4 + 2] = __uint_as_float(h); Qlo[rr * QST + c4 + 2] = __uint_as_float(l);
        split_tf32(vq.w, h, l); Qhi[rr * QST + c4 + 3] = __uint_as_float(h); Qlo[rr * QST + c4 + 3] = __uint_as_float(l);
    }
    float oacc[8][4];
#pragma unroll
    for (int nt = 0; nt < 8; ++nt)
#pragma unroll
        for (int r = 0; r < 4; ++r) oacc[nt][r] = 0.f;
    float mrow = -INFINITY, lrow = 0.f;

    for (int kt = 0; kt <= qt; ++kt) {
        const int kr0 = kt * 64;
        __syncthreads();   // prior PV done (and Q staged, first iter)
        // stage K, pre-split
        for (int it = tid; it < 2048; it += 256) {
            int rr = it >> 5, c4 = (it & 31) << 2;
            float4 vk = *(const float4*)(k + (size_t)(kr0 + rr) * (N_KVH * HD) + kvh * HD + c4);
            uint32_t h, l;
            split_tf32(vk.x, h, l); KVhi[rr * QST + c4 + 0] = __uint_as_float(h); KVlo[rr * QST + c4 + 0] = __uint_as_float(l);
            split_tf32(vk.y, h, l); KVhi[rr * QST + c4 + 1] = __uint_as_float(h); KVlo[rr * QST + c4 + 1] = __uint_as_float(l);
            split_tf32(vk.z, h, l); KVhi[rr * QST + c4 + 2] = __uint_as_float(h); KVlo[rr * QST + c4 + 2] = __uint_as_float(l);
            split_tf32(vk.w, h, l); KVhi[rr * QST + c4 + 3] = __uint_as_float(h); KVlo[rr * QST + c4 + 3] = __uint_as_float(l);
        }
        __syncthreads();
        // S = Q K^T (tf32x3), warp tile 16x32
        float sc[4][4];
#pragma unroll
        for (int nt = 0; nt < 4; ++nt)
#pragma unroll
            for (int r = 0; r < 4; ++r) sc[nt][r] = 0.f;
#pragma unroll
        for (int k8 = 0; k8 < 16; ++k8) {
            uint32_t ah[4], al[4];
#pragma unroll
            for (int j = 0; j < 4; ++j) {
                int kidx = k8 * 8 + gc + ((j >> 1) << 2);
                int midx = wms + gr + ((j & 1) << 3);
                ah[j] = __float_as_uint(Qhi[midx * QST + kidx]);
                al[j] = __float_as_uint(Qlo[midx * QST + kidx]);
            }
#pragma unroll
            for (int nt = 0; nt < 4; ++nt) {
                int nidx = wns + nt * 8 + gr;
                uint32_t bh[2], bl[2];
#pragma unroll
                for (int j = 0; j < 2; ++j) {
                    int kidx = k8 * 8 + gc + (j << 2);
                    bh[j] = __float_as_uint(KVhi[nidx * QST + kidx]);
                    bl[j] = __float_as_uint(KVlo[nidx * QST + kidx]);
                }
                float* c = sc[nt];
                MMA_TF32(c[0], c[1], c[2], c[3], ah[0], ah[1], ah[2], ah[3], bl[0], bl[1]);
                MMA_TF32(c[0], c[1], c[2], c[3], al[0], al[1], al[2], al[3], bh[0], bh[1]);
                MMA_TF32(c[0], c[1], c[2], c[3], ah[0], ah[1], ah[2], ah[3], bh[0], bh[1]);
            }
        }
        // write raw S to Phi scratch
#pragma unroll
        for (int nt = 0; nt < 4; ++nt) {
            int cb = wns + nt * 8 + gc * 2;
            *(float2*)&Phi[(wms + gr) * PST + cb] = make_float2(sc[nt][0], sc[nt][1]);
            *(float2*)&Phi[(wms + gr + 8) * PST + cb] = make_float2(sc[nt][2], sc[nt][3]);
        }
        __syncthreads();
        // stage V (over K buffer), pre-split — independent of softmax below
        for (int it = tid; it < 2048; it += 256) {
            int rr = it >> 5, c4 = (it & 31) << 2;
            float4 vv = *(const float4*)(v + (size_t)(kr0 + rr) * (N_KVH * HD) + kvh * HD + c4);
            uint32_t h, l;
            split_tf32(vv.x, h, l); KVhi[rr * QST + c4 + 0] = __uint_as_float(h); KVlo[rr * QST + c4 + 0] = __uint_as_float(l);
            split_tf32(vv.y, h, l); KVhi[rr * QST + c4 + 1] = __uint_as_float(h); KVlo[rr * QST + c4 + 1] = __uint_as_float(l);
            split_tf32(vv.z, h, l); KVhi[rr * QST + c4 + 2] = __uint_as_float(h); KVlo[rr * QST + c4 + 2] = __uint_as_float(l);
            split_tf32(vv.w, h, l); KVhi[rr * QST + c4 + 3] = __uint_as_float(h); KVlo[rr * QST + c4 + 3] = __uint_as_float(l);
        }
        // online softmax (validated flash2 logic), P split into Phi/Plo
        {
            float s[16];
#pragma unroll
            for (int jj = 0; jj < 16; ++jj) s[jj] = Phi[sr * PST + sg * 16 + jj];
            float mx = -INFINITY;
#pragma unroll
            for (int jj = 0; jj < 16; ++jj) {
                int col = kr0 + sg * 16 + jj;
                float sv = (col <= qr0 + sr) ? s[jj] * scale : -INFINITY;
                s[jj] = sv;
                mx = fmaxf(mx, sv);
            }
            mx = fmaxf(mx, __shfl_xor_sync(0xffffffffu, mx, 1));
            mx = fmaxf(mx, __shfl_xor_sync(0xffffffffu, mx, 2));
            float nm = fmaxf(mrow, mx);
            float rs = 0.f;
#pragma unroll
            for (int jj = 0; jj < 16; ++jj) {
                float pv = expf(s[jj] - nm);
                rs += pv;
                uint32_t h, l;
                split_tf32(pv, h, l);
                Phi[sr * PST + sg * 16 + jj] = __uint_as_float(h);
                Plo[sr * PST + sg * 16 + jj] = __uint_as_float(l);
            }
            rs += __shfl_xor_sync(0xffffffffu, rs, 1);
            rs += __shfl_xor_sync(0xffffffffu, rs, 2);
            float alpha = expf(mrow - nm);
            lrow = lrow * alpha + rs;
            mrow = nm;
            if (sg == 0) salpha[sr] = alpha;
        }
        __syncthreads();
        // rescale O, then O += P V (tf32x3), warp tile 16x64
        {
            float a0 = salpha[wms + gr], a1 = salpha[wms + gr + 8];
#pragma unroll
            for (int nt = 0; nt < 8; ++nt) {
                oacc[nt][0] *= a0; oacc[nt][1] *= a0;
                oacc[nt][2] *= a1; oacc[nt][3] *= a1;
            }
        }
#pragma unroll
        for (int k8 = 0; k8 < 8; ++k8) {
            uint32_t ah[4], al[4];
#pragma unroll
            for (int j = 0; j < 4; ++j) {
                int kidx = k8 * 8 + gc + ((j >> 1) << 2);
                int midx = wms + gr + ((j & 1) << 3);
                ah[j] = __float_as_uint(Phi[midx * PST + kidx]);
                al[j] = __float_as_uint(Plo[midx * PST + kidx]);
            }
#pragma unroll
            for (int nt = 0; nt < 8; ++nt) {
                int nidx = wno + nt * 8 + gr;
                uint32_t bh[2], bl[2];
#pragma unroll
                for (int j = 0; j < 2; ++j) {
                    int kidx = k8 * 8 + gc + (j << 2);
                    bh[j] = __float_as_uint(KVhi[kidx * QST + nidx]);
                    bl[j] = __float_as_uint(KVlo[kidx * QST + nidx]);
                }
                float* c = oacc[nt];
                MMA_TF32(c[0], c[1], c[2], c[3], ah[0], ah[1], ah[2], ah[3], bl[0], bl[1]);
                MMA_TF32(c[0], c[1], c[2], c[3], al[0], al[1], al[2], al[3], bh[0], bh[1]);
                MMA_TF32(c[0], c[1], c[2], c[3], ah[0], ah[1], ah[2], ah[3], bh[0], bh[1]);
            }
        }
    }
    // final normalize + store
    __syncthreads();
    if (sg == 0) salpha[sr] = 1.f / lrow;
    __syncthreads();
    float i0 = salpha[wms + gr], i1 = salpha[wms + gr + 8];
#pragma unroll
    for (int nt = 0; nt < 8; ++nt) {
        int cb = head * HD + wno + nt * 8 + gc * 2;
        *(float2*)(o + (size_t)(qr0 + wms + gr) * (N_H * HD) + cb) =
            make_float2(oacc[nt][0] * i0, oacc[nt][1] * i0);
        *(float2*)(o + (size_t)(qr0 + wms + gr + 8) * (N_H * HD) + cb) =
            make_float2(oacc[nt][2] * i1, oacc[nt][3] * i1);
    }
}

// ---------------- router: logits -> softmax -> top2 -> scatter ----------------
__global__ void router_kernel(const float* __restrict__ x, const float* __restrict__ gw,
                              int* __restrict__ cnt, int* __restrict__ tok,
                              float* __restrict__ wt) {
    int t = blockIdx.x;
    const float* xr = x + (size_t)t * D_DIM;
    float acc[8] = {0, 0, 0, 0, 0, 0, 0, 0};
    for (int d = threadIdx.x; d < D_DIM; d += 256) {
        float xv = xr[d];
        const float4* g4 = (const float4*)(gw + (size_t)d * N_E);
        float4 a = g4[0], b = g4[1];
        acc[0] = fmaf(xv, a.x, acc[0]); acc[1] = fmaf(xv, a.y, acc[1]);
        acc[2] = fmaf(xv, a.z, acc[2]); acc[3] = fmaf(xv, a.w, acc[3]);
        acc[4] = fmaf(xv, b.x, acc[4]); acc[5] = fmaf(xv, b.y, acc[5]);
        acc[6] = fmaf(xv, b.z, acc[6]); acc[7] = fmaf(xv, b.w, acc[7]);
    }
    __shared__ float smr[8][256];
#pragma unroll
    for (int e = 0; e < 8; ++e) smr[e][threadIdx.x] = acc[e];
    __syncthreads();
    for (int s = 128; s; s >>= 1) {
        if (threadIdx.x < s)
#pragma unroll
            for (int e = 0; e < 8; ++e) smr[e][threadIdx.x] += smr[e][threadIdx.x + s];
        __syncthreads();
    }
    if (threadIdx.x == 0) {
        float l[8], p[8];
        float mx = -1e30f;
#pragma unroll
        for (int e = 0; e < 8; ++e) { l[e] = smr[e][0]; mx = fmaxf(mx, l[e]); }
        float ssum = 0.f;
#pragma unroll
        for (int e = 0; e < 8; ++e) { p[e] = expf(l[e] - mx); ssum += p[e]; }
#pragma unroll
        for (int e = 0; e < 8; ++e) p[e] /= ssum;
        int i0 = 0; float p0 = p[0];
#pragma unroll
        for (int e = 1; e < 8; ++e) if (p[e] > p0) { p0 = p[e]; i0 = e; }
        int i1 = -1; float p1 = -1.f;
#pragma unroll
        for (int e = 0; e < 8; ++e) if (e != i0 && p[e] > p1) { p1 = p[e]; i1 = e; }
        float wn = p0 + p1;
        int pos = atomicAdd(&cnt[i0], 1);
        tok[i0 * T_TOK + pos] = t; wt[i0 * T_TOK + pos] = p0 / wn;
        pos = atomicAdd(&cnt[i1], 1);
        tok[i1 * T_TOK + pos] = t; wt[i1 * T_TOK + pos] = p1 / wn;
    }
}

// ---------------- silu(g)*u, only over active rows per expert ----------------
__global__ void silu_mul_kernel(float* __restrict__ g, const float* __restrict__ u,
                                const int* __restrict__ cnt) {
    int e = blockIdx.z;
    int row = blockIdx.y;
    if (row >= cnt[e]) return;
    size_t base = ((size_t)e * T_TOK + row) * I_DIM;
    int i = blockIdx.x * 256 + threadIdx.x;
    float4 gv = ((const float4*)(g + base))[i];
    float4 uv = ((const float4*)(u + base))[i];
    gv.x = gv.x / (1.f + __expf(-gv.x)) * uv.x;
    gv.y = gv.y / (1.f + __expf(-gv.y)) * uv.y;
    gv.z = gv.z / (1.f + __expf(-gv.z)) * uv.z;
    gv.w = gv.w / (1.f + __expf(-gv.w)) * uv.w;
    ((float4*)(g + base))[i] = gv;
}

// ---------------- launch ----------------
extern "C" void kernel_launch(void* const* d_in, const int* in_sizes, int n_in,
                              void* d_out, int out_size) {
    const float* hidden = (const float*)d_in[0];
    const int* positions = (const int*)d_in[1];
    const float* ln1 = (const float*)d_in[2];
    const float* ln2 = (const float*)d_in[3];
    const float* wq = (const float*)d_in[4];
    const float* bq = (const float*)d_in[5];
    const float* wk = (const float*)d_in[6];
    const float* bk = (const float*)d_in[7];
    const float* wv = (const float*)d_in[8];
    const float* bv = (const float*)d_in[9];
    const float* wo = (const float*)d_in[10];
    const float* gate_w = (const float*)d_in[11];
    const float* w_gate = (const float*)d_in[12];
    const float* w_up = (const float*)d_in[13];
    const float* w_down = (const float*)d_in[14];
    float* out = (float*)d_out;

    float *xnorm, *q, *k, *v, *attn, *x2, *gbuf, *ubuf, *wt, *ctab, *stab;
    int *cnt, *tok;
    cudaGetSymbolAddress((void**)&xnorm, g_xnorm);
    cudaGetSymbolAddress((void**)&q, g_q);
    cudaGetSymbolAddress((void**)&k, g_k);
    cudaGetSymbolAddress((void**)&v, g_v);
    cudaGetSymbolAddress((void**)&attn, g_attn);
    cudaGetSymbolAddress((void**)&x2, g_x2);
    cudaGetSymbolAddress((void**)&gbuf, g_gbuf);
    cudaGetSymbolAddress((void**)&ubuf, g_ubuf);
    cudaGetSymbolAddress((void**)&cnt, g_cnt);
    cudaGetSymbolAddress((void**)&tok, g_tok);
    cudaGetSymbolAddress((void**)&wt, g_wt);
    cudaGetSymbolAddress((void**)&ctab, g_cos);
    cudaGetSymbolAddress((void**)&stab, g_sin);

    const int smem_f3 = (4 * 64 * QST + 2 * 64 * PST + 64) * sizeof(float);
    cudaFuncSetAttribute(flash3_kernel, cudaFuncAttributeMaxDynamicSharedMemorySize, smem_f3);

    // 0) RoPE table (accurate trig)
    rope_table_kernel<<<T_TOK, 64>>>(positions, ctab, stab);
    // 1) RMSNorm 1
    rmsnorm_kernel<<<T_TOK, 256>>>(hidden, ln1, xnorm);
    // 2) Q projection (+bias); K+V fused via DUAL
    tgemm_kernel<0, false, false><<<dim3(16, 16, 1), 256>>>(
        xnorm, wq, q, T_TOK, 2048, 2048, bq, nullptr, nullptr, nullptr, nullptr,
        0, 0, 0, nullptr, nullptr, nullptr);
    tgemm_kernel<0, false, true><<<dim3(4, 16, 2), 256>>>(
        xnorm, wk, k, T_TOK, 512, 2048, bk, nullptr, nullptr, nullptr, nullptr,
        0, 0, 0, wv, v, bv);
    // 3) RoPE apply
    rope_apply_kernel<<<dim3(T_TOK, N_H), 64>>>(q, ctab, stab, N_H);
    rope_apply_kernel<<<dim3(T_TOK, N_KVH), 64>>>(k, ctab, stab, N_KVH);
    // 4) attention (tensor-core)
    flash3_kernel<<<dim3(T_TOK / 64, N_H), 256, smem_f3>>>(q, k, v, attn);
    // 5) output proj + residual -> d_out holds h
    tgemm_kernel<1, false, false><<<dim3(16, 16, 1), 256>>>(
        attn, wo, out, T_TOK, 2048, 2048, nullptr, hidden, nullptr, nullptr, nullptr,
        0, 0, 0, nullptr, nullptr, nullptr);
    // 6) RMSNorm 2
    rmsnorm_kernel<<<T_TOK, 256>>>(out, ln2, x2);
    // 7) router
    cudaMemsetAsync(cnt, 0, N_E * sizeof(int));
    router_kernel<<<T_TOK, 256>>>(x2, gate_w, cnt, tok, wt);
    // 8) expert gate+up fused via DUAL (gathered rows, early-exit on count)
    tgemm_kernel<2, true, true><<<dim3(I_DIM / 128, T_TOK / 128, N_E * 2), 256>>>(
        x2, w_gate, gbuf, 0, I_DIM, D_DIM, nullptr, nullptr, cnt, tok, nullptr,
        0, (long)D_DIM * I_DIM, (long)T_TOK * I_DIM, w_up, ubuf, nullptr);
    // 9) silu(g)*u on active rows only
    silu_mul_kernel<<<dim3(1, T_TOK, N_E), 256>>>(gbuf, ubuf, cnt);
    // 10) expert down GEMM, scatter *weight into d_out (residual already there)
    tgemm_kernel<3, false, false><<<dim3(D_DIM / 128, T_TOK / 128, N_E), 256>>>(
        gbuf, w_down, out, 0, D_DIM, I_DIM, nullptr, nullptr, cnt, tok, wt,
        (long)T_TOK * I_DIM, (long)I_DIM * D_DIM, 0, nullptr, nullptr, nullptr);
}

// round 8
// speedup vs baseline: 26.1762x; 1.8144x over previous
#include <cuda_runtime.h>
#include <cuda_bf16.h>
#include <math.h>
#include <stdint.h>

#define T_TOK 2048
#define D_DIM 2048
#define N_H   16
#define N_KVH 4
#define HD    128
#define N_E   8
#define I_DIM 1024

// ---------------- scratch (static device globals; allocation-free) ----------------
__device__ float g_xnorm[T_TOK * D_DIM];
__device__ float g_q[T_TOK * N_H * HD];
__device__ float g_k[T_TOK * N_KVH * HD];
__device__ float g_v[T_TOK * N_KVH * HD];
__device__ float g_attn[T_TOK * N_H * HD];
__device__ float g_x2[T_TOK * D_DIM];
__device__ float g_gbuf[N_E * T_TOK * I_DIM];
__device__ float g_ubuf[N_E * T_TOK * I_DIM];
__device__ int   g_cnt[N_E];
__device__ int   g_tok[N_E * T_TOK];
__device__ float g_wt[N_E * T_TOK];
__device__ float g_cos[T_TOK * 64];
__device__ float g_sin[T_TOK * 64];

// ---------------- bf16 split helpers ----------------
// pack two floats (x->low k, y->high k) as bf16 hi pair; lo pair via out-param.
__device__ __forceinline__ uint32_t pack2bf(float x, float y, uint32_t& lo) {
    __nv_bfloat162 h2 = __floats2bfloat162_rn(x, y);
    float2 hf = __bfloat1622float2(h2);
    __nv_bfloat162 l2 = __floats2bfloat162_rn(x - hf.x, y - hf.y);
    lo = *reinterpret_cast<uint32_t*>(&l2);
    return *reinterpret_cast<uint32_t*>(&h2);
}

#define MMA_BF16(c0, c1, c2, c3, a0, a1, a2, a3, b0, b1)                         \
    asm volatile(                                                                \
        "mma.sync.aligned.m16n8k16.row.col.f32.bf16.bf16.f32 "                   \
        "{%0,%1,%2,%3}, {%4,%5,%6,%7}, {%8,%9}, {%0,%1,%2,%3};\n"                \
        : "+f"(c0), "+f"(c1), "+f"(c2), "+f"(c3)                                 \
        : "r"(a0), "r"(a1), "r"(a2), "r"(a3), "r"(b0), "r"(b1))

// ---------------- RMSNorm ----------------
__global__ void rmsnorm_kernel(const float* __restrict__ x, const float* __restrict__ w,
                               float* __restrict__ out) {
    int row = blockIdx.x, tid = threadIdx.x;
    const float4* xr = (const float4*)(x + (size_t)row * D_DIM);
    const float4* wr = (const float4*)w;
    float ss = 0.f;
#pragma unroll
    for (int p = 0; p < 2; ++p) {
        float4 v = xr[tid + p * 256];
        ss += v.x * v.x + v.y * v.y + v.z * v.z + v.w * v.w;
    }
#pragma unroll
    for (int o = 16; o; o >>= 1) ss += __shfl_xor_sync(0xffffffffu, ss, o);
    __shared__ float red[8];
    if ((tid & 31) == 0) red[tid >> 5] = ss;
    __syncthreads();
    float tot = 0.f;
#pragma unroll
    for (int i = 0; i < 8; ++i) tot += red[i];
    float inv = rsqrtf(tot * (1.0f / D_DIM) + 1e-6f);
    float4* o4 = (float4*)(out + (size_t)row * D_DIM);
#pragma unroll
    for (int p = 0; p < 2; ++p) {
        int i = tid + p * 256;
        float4 v = xr[i], wv = wr[i];
        o4[i] = make_float4(v.x * inv * wv.x, v.y * inv * wv.y,
                            v.z * inv * wv.z, v.w * inv * wv.w);
    }
}

// ---------------- bf16x3 tensor-core GEMM (packed-pair smem, BK=32) ----------------
// EPI: 0 = +bias store, 1 = +residual store, 2 = plain store, 3 = atomic scatter *weight
// NMAT: 1..3 output matrices selected by blockIdx.x bands (nb0, nb1).
#define APS 132
#define BPS 132
template <int EPI, bool GATHER, int NMAT>
__global__ void __launch_bounds__(256)
tgemm_kernel(const float* __restrict__ A,
             const float* __restrict__ Bm0, const float* __restrict__ Bm1,
             const float* __restrict__ Bm2,
             float* __restrict__ Cm0, float* __restrict__ Cm1, float* __restrict__ Cm2,
             const float* __restrict__ bi0, const float* __restrict__ bi1,
             const float* __restrict__ bi2,
             int M, int Kd, int N0a, int N1a, int N2a, int nb0, int nb1,
             const float* __restrict__ res,
             const int* __restrict__ cnt, const int* __restrict__ tok,
             const float* __restrict__ wt,
             long aBatch, long bBatch, long cBatch) {
    __shared__ uint32_t Ah[16 * APS], Al[16 * APS];  // [kpair][m]
    __shared__ uint32_t Bh[16 * BPS], Bl[16 * BPS];  // [kpair][n]
    const int e = blockIdx.z;
    const int Mcur = cnt ? cnt[e] : M;
    const int m0 = blockIdx.y * 128;
    if (m0 >= Mcur) return;
    int bx = blockIdx.x;
    const float* Bsel;
    float* Csel;
    const float* bsel;
    int N;
    if (NMAT == 1 || bx < nb0) {
        Bsel = Bm0; Csel = Cm0; bsel = bi0; N = N0a;
    } else if (NMAT == 2 || bx < nb0 + nb1) {
        bx -= nb0; Bsel = Bm1; Csel = Cm1; bsel = bi1; N = N1a;
    } else {
        bx -= nb0 + nb1; Bsel = Bm2; Csel = Cm2; bsel = bi2; N = N2a;
    }
    const int n0 = bx * 128;
    const float* Ab = A + (size_t)e * aBatch;
    const float* Bb = Bsel + (size_t)e * bBatch;
    float* Cb = Csel + (size_t)e * cBatch;
    const int* tokb = tok ? tok + e * T_TOK : nullptr;
    const int tid = threadIdx.x;
    const int lane = tid & 31, warp = tid >> 5;
    const int warp_m = (warp >> 2) * 64, warp_n = (warp & 3) * 32;
    const int gr = lane >> 2, gc = lane & 3;

    // A staging rows: row = (tid>>3) + p*32
    const int r0 = tid >> 3;
    const int ac4 = (tid & 7) << 2;
    int arow[4];
    bool av[4];
#pragma unroll
    for (int p = 0; p < 4; ++p) {
        int rg = m0 + r0 + p * 32;
        av[p] = rg < Mcur;
        arow[p] = av[p] ? (GATHER ? tokb[rg] : rg) : 0;
    }

    float acc[4][4][4];
#pragma unroll
    for (int mt = 0; mt < 4; ++mt)
#pragma unroll
        for (int nt = 0; nt < 4; ++nt)
#pragma unroll
            for (int r = 0; r < 4; ++r) acc[mt][nt][r] = 0.f;

    for (int kk = 0; kk < Kd; kk += 32) {
        // stage A [kpair][m]
#pragma unroll
        for (int p = 0; p < 4; ++p) {
            float4 va = make_float4(0.f, 0.f, 0.f, 0.f);
            if (av[p]) va = *(const float4*)(Ab + (size_t)arow[p] * Kd + kk + ac4);
            int row = r0 + p * 32;
            int kp = ac4 >> 1;
            uint32_t l0, l1;
            uint32_t h0 = pack2bf(va.x, va.y, l0);
            uint32_t h1 = pack2bf(va.z, va.w, l1);
            Ah[kp * APS + row] = h0;       Al[kp * APS + row] = l0;
            Ah[(kp + 1) * APS + row] = h1; Al[(kp + 1) * APS + row] = l1;
        }
        // stage B [kpair][n] (pairs along k from two gmem rows)
#pragma unroll
        for (int p = 0; p < 2; ++p) {
            int idx = tid + p * 256;
            int kp = idx >> 5;
            int c4 = (idx & 31) << 2;
            const float* brow = Bb + (size_t)(kk + 2 * kp) * N + n0 + c4;
            float4 v0 = *(const float4*)brow;
            float4 v1 = *(const float4*)(brow + N);
            uint32_t h0, h1, h2, h3, l0, l1, l2, l3;
            h0 = pack2bf(v0.x, v1.x, l0);
            h1 = pack2bf(v0.y, v1.y, l1);
            h2 = pack2bf(v0.z, v1.z, l2);
            h3 = pack2bf(v0.w, v1.w, l3);
            *(uint4*)&Bh[kp * BPS + c4] = make_uint4(h0, h1, h2, h3);
            *(uint4*)&Bl[kp * BPS + c4] = make_uint4(l0, l1, l2, l3);
        }
        __syncthreads();
#pragma unroll
        for (int s = 0; s < 2; ++s) {
            const int kpb = s * 8;
            uint32_t ah[4][4], al[4][4];
#pragma unroll
            for (int mt = 0; mt < 4; ++mt) {
                int m = warp_m + mt * 16 + gr;
                int i0 = (kpb + gc) * APS + m, i1 = (kpb + gc + 4) * APS + m;
                ah[mt][0] = Ah[i0];     ah[mt][1] = Ah[i0 + 8];
                ah[mt][2] = Ah[i1];     ah[mt][3] = Ah[i1 + 8];
                al[mt][0] = Al[i0];     al[mt][1] = Al[i0 + 8];
                al[mt][2] = Al[i1];     al[mt][3] = Al[i1 + 8];
            }
            uint32_t bh[4][2], bl[4][2];
#pragma unroll
            for (int nt = 0; nt < 4; ++nt) {
                int n = warp_n + nt * 8 + gr;
                bh[nt][0] = Bh[(kpb + gc) * BPS + n];
                bh[nt][1] = Bh[(kpb + gc + 4) * BPS + n];
                bl[nt][0] = Bl[(kpb + gc) * BPS + n];
                bl[nt][1] = Bl[(kpb + gc + 4) * BPS + n];
            }
#pragma unroll
            for (int mt = 0; mt < 4; ++mt)
#pragma unroll
                for (int nt = 0; nt < 4; ++nt) {
                    float* c = acc[mt][nt];
                    MMA_BF16(c[0], c[1], c[2], c[3],
                             ah[mt][0], ah[mt][1], ah[mt][2], ah[mt][3],
                             bl[nt][0], bl[nt][1]);
                    MMA_BF16(c[0], c[1], c[2], c[3],
                             al[mt][0], al[mt][1], al[mt][2], al[mt][3],
                             bh[nt][0], bh[nt][1]);
                    MMA_BF16(c[0], c[1], c[2], c[3],
                             ah[mt][0], ah[mt][1], ah[mt][2], ah[mt][3],
                             bh[nt][0], bh[nt][1]);
                }
        }
        __syncthreads();
    }

#pragma unroll
    for (int mt = 0; mt < 4; ++mt) {
#pragma unroll
        for (int rr = 0; rr < 2; ++rr) {
            int rg = m0 + warp_m + mt * 16 + gr + rr * 8;
            if (rg >= Mcur) continue;
            if (EPI == 3) {
                int t = tokb[rg];
                float w = wt[e * T_TOK + rg];
                float* outr = Cm0 + (size_t)t * N;
#pragma unroll
                for (int nt = 0; nt < 4; ++nt) {
                    int cb = n0 + warp_n + nt * 8 + gc * 2;
                    atomicAdd(&outr[cb], acc[mt][nt][rr * 2] * w);
                    atomicAdd(&outr[cb + 1], acc[mt][nt][rr * 2 + 1] * w);
                }
            } else {
#pragma unroll
                for (int nt = 0; nt < 4; ++nt) {
                    int cb = n0 + warp_n + nt * 8 + gc * 2;
                    float v0 = acc[mt][nt][rr * 2], v1 = acc[mt][nt][rr * 2 + 1];
                    if (EPI == 0) { v0 += bsel[cb]; v1 += bsel[cb + 1]; }
                    if (EPI == 1) {
                        const float* rrow = res + (size_t)rg * N;
                        v0 += rrow[cb]; v1 += rrow[cb + 1];
                    }
                    *(float2*)(Cb + (size_t)rg * N + cb) = make_float2(v0, v1);
                }
            }
        }
    }
}

// ---------------- RoPE: accurate table (double trig) + f32 apply ----------------
__global__ void rope_table_kernel(const int* __restrict__ pos,
                                  float* __restrict__ ctab, float* __restrict__ stab) {
    int t = blockIdx.x, i = threadIdx.x;  // 64 threads
    float p = (float)pos[t];
    float invf = (float)exp(-(double)i * (13.815510557964274 / 64.0));
    float fr = p * invf;
    double cd = cos((double)fr), sd = sin((double)fr);
    ctab[t * 64 + i] = (float)cd;
    stab[t * 64 + i] = (float)sd;
}

__global__ void rope_apply_kernel(float* __restrict__ x, const float* __restrict__ ctab,
                                  const float* __restrict__ stab, int nheads) {
    int t = blockIdx.x, h = blockIdx.y, i = threadIdx.x;  // 64 threads
    float c = ctab[t * 64 + i], s = stab[t * 64 + i];
    float* b = x + ((size_t)t * nheads + h) * HD;
    float x1 = b[i], x2 = b[i + 64];
    b[i] = x1 * c - x2 * s;
    b[i + 64] = x2 * c + x1 * s;
}

// ---------------- flash attention v4: bf16x3 tensor cores, validated softmax ----------------
#define QPS 69    // [dpair][row/key] stride (uint32)
#define VPS 132   // [keypair][d] stride (uint32)
#define SST 68    // S scratch stride (float)
#define PPS 69    // [keypair][row] stride (uint32)
__global__ void __launch_bounds__(256)
flash4_kernel(const float* __restrict__ q, const float* __restrict__ k,
              const float* __restrict__ v, float* __restrict__ o) {
    extern __shared__ uint32_t sm4[];
    uint32_t* Qh = sm4;                    // 64*QPS
    uint32_t* Ql = Qh + 64 * QPS;
    uint32_t* Kh = Ql + 64 * QPS;          // K [dpair][key]; reused as V [keypair][d]
    uint32_t* Kl = Kh + 64 * QPS;
    float* Ss = (float*)(Kl + 64 * QPS);   // 64*SST
    uint32_t* Ph = (uint32_t*)(Ss + 64 * SST);  // 32*PPS
    uint32_t* Pl = Ph + 32 * PPS;
    float* salpha = (float*)(Pl + 32 * PPS);    // 64
    const int tid = threadIdx.x;
    const int lane = tid & 31, warp = tid >> 5;
    const int gr = lane >> 2, gc = lane & 3;
    const int wms = (warp >> 1) * 16;          // S/O warp row base
    const int wns = (warp & 1) * 32;           // S warp col base
    const int wno = (warp & 1) * 64;           // O warp col base
    const int sr = tid >> 2, sg = tid & 3;     // softmax role
    const int qt = blockIdx.x, head = blockIdx.y, kvh = head >> 2;
    const int qr0 = qt * 64;
    const float scale = 0.08838834764831845f;

    // stage Q packed [dpair][row] (reused across kt)
#pragma unroll
    for (int p = 0; p < 8; ++p) {
        int idx = tid + p * 256;
        int row = idx >> 5, c4 = (idx & 31) << 2;
        float4 vq = *(const float4*)(q + (size_t)(qr0 + row) * (N_H * HD) + head * HD + c4);
        int dp = c4 >> 1;
        uint32_t l0, l1;
        uint32_t h0 = pack2bf(vq.x, vq.y, l0);
        uint32_t h1 = pack2bf(vq.z, vq.w, l1);
        Qh[dp * QPS + row] = h0;       Ql[dp * QPS + row] = l0;
        Qh[(dp + 1) * QPS + row] = h1; Ql[(dp + 1) * QPS + row] = l1;
    }
    float oacc[8][4];
#pragma unroll
    for (int nt = 0; nt < 8; ++nt)
#pragma unroll
        for (int r = 0; r < 4; ++r) oacc[nt][r] = 0.f;
    float mrow = -INFINITY, lrow = 0.f;

    for (int kt = 0; kt <= qt; ++kt) {
        const int kr0 = kt * 64;
        __syncthreads();  // prior PV done (and Q staged on first iter)
        // stage K packed [dpair][key]
#pragma unroll
        for (int p = 0; p < 8; ++p) {
            int idx = tid + p * 256;
            int key = idx >> 5, c4 = (idx & 31) << 2;
            float4 vk = *(const float4*)(k + (size_t)(kr0 + key) * (N_KVH * HD) + kvh * HD + c4);
            int dp = c4 >> 1;
            uint32_t l0, l1;
            uint32_t h0 = pack2bf(vk.x, vk.y, l0);
            uint32_t h1 = pack2bf(vk.z, vk.w, l1);
            Kh[dp * QPS + key] = h0;       Kl[dp * QPS + key] = l0;
            Kh[(dp + 1) * QPS + key] = h1; Kl[(dp + 1) * QPS + key] = l1;
        }
        __syncthreads();
        // S = Q K^T (bf16x3): warp tile 16x32, 8 k16-steps over d=128
        float sc[4][4];
#pragma unroll
        for (int nt = 0; nt < 4; ++nt)
#pragma unroll
            for (int r = 0; r < 4; ++r) sc[nt][r] = 0.f;
#pragma unroll
        for (int ks = 0; ks < 8; ++ks) {
            const int kpb = ks * 8;
            uint32_t ah[4], al[4];
            {
                int m = wms + gr;
                int i0 = (kpb + gc) * QPS + m, i1 = (kpb + gc + 4) * QPS + m;
                ah[0] = Qh[i0]; ah[1] = Qh[i0 + 8]; ah[2] = Qh[i1]; ah[3] = Qh[i1 + 8];
                al[0] = Ql[i0]; al[1] = Ql[i0 + 8]; al[2] = Ql[i1]; al[3] = Ql[i1 + 8];
            }
#pragma unroll
            for (int nt = 0; nt < 4; ++nt) {
                int n = wns + nt * 8 + gr;
                uint32_t bh0 = Kh[(kpb + gc) * QPS + n];
                uint32_t bh1 = Kh[(kpb + gc + 4) * QPS + n];
                uint32_t bl0 = Kl[(kpb + gc) * QPS + n];
                uint32_t bl1 = Kl[(kpb + gc + 4) * QPS + n];
                float* c = sc[nt];
                MMA_BF16(c[0], c[1], c[2], c[3], ah[0], ah[1], ah[2], ah[3], bl0, bl1);
                MMA_BF16(c[0], c[1], c[2], c[3], al[0], al[1], al[2], al[3], bh0, bh1);
                MMA_BF16(c[0], c[1], c[2], c[3], ah[0], ah[1], ah[2], ah[3], bh0, bh1);
            }
        }
#pragma unroll
        for (int nt = 0; nt < 4; ++nt) {
            int cb = wns + nt * 8 + gc * 2;
            *(float2*)&Ss[(wms + gr) * SST + cb] = make_float2(sc[nt][0], sc[nt][1]);
            *(float2*)&Ss[(wms + gr + 8) * SST + cb] = make_float2(sc[nt][2], sc[nt][3]);
        }
        __syncthreads();
        // stage V packed [keypair][d] over K buffer
#pragma unroll
        for (int p = 0; p < 4; ++p) {
            int idx = tid + p * 256;
            int kp = idx >> 5, c4 = (idx & 31) << 2;
            const float* vrow = v + (size_t)(kr0 + 2 * kp) * (N_KVH * HD) + kvh * HD + c4;
            float4 v0 = *(const float4*)vrow;
            float4 v1 = *(const float4*)(vrow + N_KVH * HD);
            uint32_t h0, h1, h2, h3, l0, l1, l2, l3;
            h0 = pack2bf(v0.x, v1.x, l0);
            h1 = pack2bf(v0.y, v1.y, l1);
            h2 = pack2bf(v0.z, v1.z, l2);
            h3 = pack2bf(v0.w, v1.w, l3);
            *(uint4*)&Kh[kp * VPS + c4] = make_uint4(h0, h1, h2, h3);
            *(uint4*)&Kl[kp * VPS + c4] = make_uint4(l0, l1, l2, l3);
        }
        // online softmax (validated), P packed into Ph/Pl
        {
            float s[16];
#pragma unroll
            for (int jj = 0; jj < 16; ++jj) s[jj] = Ss[sr * SST + sg * 16 + jj];
            float mx = -INFINITY;
#pragma unroll
            for (int jj = 0; jj < 16; ++jj) {
                int col = kr0 + sg * 16 + jj;
                float sv = (col <= qr0 + sr) ? s[jj] * scale : -INFINITY;
                s[jj] = sv;
                mx = fmaxf(mx, sv);
            }
            mx = fmaxf(mx, __shfl_xor_sync(0xffffffffu, mx, 1));
            mx = fmaxf(mx, __shfl_xor_sync(0xffffffffu, mx, 2));
            float nm = fmaxf(mrow, mx);
            float rs = 0.f;
#pragma unroll
            for (int jj = 0; jj < 16; ++jj) {
                s[jj] = expf(s[jj] - nm);
                rs += s[jj];
            }
#pragma unroll
            for (int qq = 0; qq < 8; ++qq) {
                uint32_t lo;
                uint32_t hi = pack2bf(s[2 * qq], s[2 * qq + 1], lo);
                Ph[(sg * 8 + qq) * PPS + sr] = hi;
                Pl[(sg * 8 + qq) * PPS + sr] = lo;
            }
            rs += __shfl_xor_sync(0xffffffffu, rs, 1);
            rs += __shfl_xor_sync(0xffffffffu, rs, 2);
            float alpha = expf(mrow - nm);
            lrow = lrow * alpha + rs;
            mrow = nm;
            if (sg == 0) salpha[sr] = alpha;
        }
        __syncthreads();
        // rescale O, then O += P V (bf16x3), warp tile 16x64, 4 k16-steps over 64 keys
        {
            float a0 = salpha[wms + gr], a1 = salpha[wms + gr + 8];
#pragma unroll
            for (int nt = 0; nt < 8; ++nt) {
                oacc[nt][0] *= a0; oacc[nt][1] *= a0;
                oacc[nt][2] *= a1; oacc[nt][3] *= a1;
            }
        }
#pragma unroll
        for (int ks = 0; ks < 4; ++ks) {
            const int kpb = ks * 8;
            uint32_t ah[4], al[4];
            {
                int m = wms + gr;
                int i0 = (kpb + gc) * PPS + m, i1 = (kpb + gc + 4) * PPS + m;
                ah[0] = Ph[i0]; ah[1] = Ph[i0 + 8]; ah[2] = Ph[i1]; ah[3] = Ph[i1 + 8];
                al[0] = Pl[i0]; al[1] = Pl[i0 + 8]; al[2] = Pl[i1]; al[3] = Pl[i1 + 8];
            }
#pragma unroll
            for (int nt = 0; nt < 8; ++nt) {
                int n = wno + nt * 8 + gr;
                uint32_t bh0 = Kh[(kpb + gc) * VPS + n];
                uint32_t bh1 = Kh[(kpb + gc + 4) * VPS + n];
                uint32_t bl0 = Kl[(kpb + gc) * VPS + n];
                uint32_t bl1 = Kl[(kpb + gc + 4) * VPS + n];
                float* c = oacc[nt];
                MMA_BF16(c[0], c[1], c[2], c[3], ah[0], ah[1], ah[2], ah[3], bl0, bl1);
                MMA_BF16(c[0], c[1], c[2], c[3], al[0], al[1], al[2], al[3], bh0, bh1);
                MMA_BF16(c[0], c[1], c[2], c[3], ah[0], ah[1], ah[2], ah[3], bh0, bh1);
            }
        }
    }
    // final normalize + store
    __syncthreads();
    if (sg == 0) salpha[sr] = 1.f / lrow;
    __syncthreads();
    float i0 = salpha[wms + gr], i1 = salpha[wms + gr + 8];
#pragma unroll
    for (int nt = 0; nt < 8; ++nt) {
        int cb = head * HD + wno + nt * 8 + gc * 2;
        *(float2*)(o + (size_t)(qr0 + wms + gr) * (N_H * HD) + cb) =
            make_float2(oacc[nt][0] * i0, oacc[nt][1] * i0);
        *(float2*)(o + (size_t)(qr0 + wms + gr + 8) * (N_H * HD) + cb) =
            make_float2(oacc[nt][2] * i1, oacc[nt][3] * i1);
    }
}

// ---------------- router: logits -> softmax -> top2 -> scatter ----------------
__global__ void router_kernel(const float* __restrict__ x, const float* __restrict__ gw,
                              int* __restrict__ cnt, int* __restrict__ tok,
                              float* __restrict__ wt) {
    int t = blockIdx.x;
    const float* xr = x + (size_t)t * D_DIM;
    float acc[8] = {0, 0, 0, 0, 0, 0, 0, 0};
    for (int d = threadIdx.x; d < D_DIM; d += 256) {
        float xv = xr[d];
        const float4* g4 = (const float4*)(gw + (size_t)d * N_E);
        float4 a = g4[0], b = g4[1];
        acc[0] = fmaf(xv, a.x, acc[0]); acc[1] = fmaf(xv, a.y, acc[1]);
        acc[2] = fmaf(xv, a.z, acc[2]); acc[3] = fmaf(xv, a.w, acc[3]);
        acc[4] = fmaf(xv, b.x, acc[4]); acc[5] = fmaf(xv, b.y, acc[5]);
        acc[6] = fmaf(xv, b.z, acc[6]); acc[7] = fmaf(xv, b.w, acc[7]);
    }
    __shared__ float smr[8][256];
#pragma unroll
    for (int e = 0; e < 8; ++e) smr[e][threadIdx.x] = acc[e];
    __syncthreads();
    for (int s = 128; s; s >>= 1) {
        if (threadIdx.x < s)
#pragma unroll
            for (int e = 0; e < 8; ++e) smr[e][threadIdx.x] += smr[e][threadIdx.x + s];
        __syncthreads();
    }
    if (threadIdx.x == 0) {
        float l[8], p[8];
        float mx = -1e30f;
#pragma unroll
        for (int e = 0; e < 8; ++e) { l[e] = smr[e][0]; mx = fmaxf(mx, l[e]); }
        float ssum = 0.f;
#pragma unroll
        for (int e = 0; e < 8; ++e) { p[e] = expf(l[e] - mx); ssum += p[e]; }
#pragma unroll
        for (int e = 0; e < 8; ++e) p[e] /= ssum;
        int i0 = 0; float p0 = p[0];
#pragma unroll
        for (int e = 1; e < 8; ++e) if (p[e] > p0) { p0 = p[e]; i0 = e; }
        int i1 = -1; float p1 = -1.f;
#pragma unroll
        for (int e = 0; e < 8; ++e) if (e != i0 && p[e] > p1) { p1 = p[e]; i1 = e; }
        float wn = p0 + p1;
        int pos = atomicAdd(&cnt[i0], 1);
        tok[i0 * T_TOK + pos] = t; wt[i0 * T_TOK + pos] = p0 / wn;
        pos = atomicAdd(&cnt[i1], 1);
        tok[i1 * T_TOK + pos] = t; wt[i1 * T_TOK + pos] = p1 / wn;
    }
}

// ---------------- silu(g)*u, only over active rows per expert ----------------
__global__ void silu_mul_kernel(float* __restrict__ g, const float* __restrict__ u,
                                const int* __restrict__ cnt) {
    int e = blockIdx.z;
    int row = blockIdx.y;
    if (row >= cnt[e]) return;
    size_t base = ((size_t)e * T_TOK + row) * I_DIM;
    int i = blockIdx.x * 256 + threadIdx.x;
    float4 gv = ((const float4*)(g + base))[i];
    float4 uv = ((const float4*)(u + base))[i];
    gv.x = gv.x / (1.f + __expf(-gv.x)) * uv.x;
    gv.y = gv.y / (1.f + __expf(-gv.y)) * uv.y;
    gv.z = gv.z / (1.f + __expf(-gv.z)) * uv.z;
    gv.w = gv.w / (1.f + __expf(-gv.w)) * uv.w;
    ((float4*)(g + base))[i] = gv;
}

// ---------------- launch ----------------
extern "C" void kernel_launch(void* const* d_in, const int* in_sizes, int n_in,
                              void* d_out, int out_size) {
    const float* hidden = (const float*)d_in[0];
    const int* positions = (const int*)d_in[1];
    const float* ln1 = (const float*)d_in[2];
    const float* ln2 = (const float*)d_in[3];
    const float* wq = (const float*)d_in[4];
    const float* bq = (const float*)d_in[5];
    const float* wk = (const float*)d_in[6];
    const float* bk = (const float*)d_in[7];
    const float* wv = (const float*)d_in[8];
    const float* bv = (const float*)d_in[9];
    const float* wo = (const float*)d_in[10];
    const float* gate_w = (const float*)d_in[11];
    const float* w_gate = (const float*)d_in[12];
    const float* w_up = (const float*)d_in[13];
    const float* w_down = (const float*)d_in[14];
    float* out = (float*)d_out;

    float *xnorm, *q, *k, *v, *attn, *x2, *gbuf, *ubuf, *wt, *ctab, *stab;
    int *cnt, *tok;
    cudaGetSymbolAddress((void**)&xnorm, g_xnorm);
    cudaGetSymbolAddress((void**)&q, g_q);
    cudaGetSymbolAddress((void**)&k, g_k);
    cudaGetSymbolAddress((void**)&v, g_v);
    cudaGetSymbolAddress((void**)&attn, g_attn);
    cudaGetSymbolAddress((void**)&x2, g_x2);
    cudaGetSymbolAddress((void**)&gbuf, g_gbuf);
    cudaGetSymbolAddress((void**)&ubuf, g_ubuf);
    cudaGetSymbolAddress((void**)&cnt, g_cnt);
    cudaGetSymbolAddress((void**)&tok, g_tok);
    cudaGetSymbolAddress((void**)&wt, g_wt);
    cudaGetSymbolAddress((void**)&ctab, g_cos);
    cudaGetSymbolAddress((void**)&stab, g_sin);

    const int smem_f4 = (4 * 64 * QPS + 64 * SST + 2 * 32 * PPS + 64) * 4;
    cudaFuncSetAttribute(flash4_kernel, cudaFuncAttributeMaxDynamicSharedMemorySize, smem_f4);

    // 0) RoPE table (accurate trig)
    rope_table_kernel<<<T_TOK, 64>>>(positions, ctab, stab);
    // 1) RMSNorm 1
    rmsnorm_kernel<<<T_TOK, 256>>>(hidden, ln1, xnorm);
    // 2) fused QKV projection (+bias): 16+4+4 n-blocks
    tgemm_kernel<0, false, 3><<<dim3(24, 16, 1), 256>>>(
        xnorm, wq, wk, wv, q, k, v, bq, bk, bv,
        T_TOK, D_DIM, 2048, 512, 512, 16, 4,
        nullptr, nullptr, nullptr, nullptr, 0, 0, 0);
    // 3) RoPE apply
    rope_apply_kernel<<<dim3(T_TOK, N_H), 64>>>(q, ctab, stab, N_H);
    rope_apply_kernel<<<dim3(T_TOK, N_KVH), 64>>>(k, ctab, stab, N_KVH);
    // 4) attention (bf16x3 tensor cores)
    flash4_kernel<<<dim3(T_TOK / 64, N_H), 256, smem_f4>>>(q, k, v, attn);
    // 5) output proj + residual -> d_out holds h
    tgemm_kernel<1, false, 1><<<dim3(16, 16, 1), 256>>>(
        attn, wo, nullptr, nullptr, out, nullptr, nullptr, nullptr, nullptr, nullptr,
        T_TOK, 2048, 2048, 0, 0, 16, 0,
        hidden, nullptr, nullptr, nullptr, 0, 0, 0);
    // 6) RMSNorm 2
    rmsnorm_kernel<<<T_TOK, 256>>>(out, ln2, x2);
    // 7) router
    cudaMemsetAsync(cnt, 0, N_E * sizeof(int));
    router_kernel<<<T_TOK, 256>>>(x2, gate_w, cnt, tok, wt);
    // 8) expert gate+up fused (gathered rows, early-exit on count)
    tgemm_kernel<2, true, 2><<<dim3(16, 16, N_E), 256>>>(
        x2, w_gate, w_up, nullptr, gbuf, ubuf, nullptr, nullptr, nullptr, nullptr,
        0, D_DIM, 1024, 1024, 0, 8, 8,
        nullptr, cnt, tok, nullptr, 0, (long)D_DIM * I_DIM, (long)T_TOK * I_DIM);
    // 9) silu(g)*u on active rows only
    silu_mul_kernel<<<dim3(1, T_TOK, N_E), 256>>>(gbuf, ubuf, cnt);
    // 10) expert down GEMM, scatter *weight into d_out (residual already there)
    tgemm_kernel<3, false, 1><<<dim3(16, 16, N_E), 256>>>(
        gbuf, w_down, nullptr, nullptr, out, nullptr, nullptr, nullptr, nullptr, nullptr,
        0, I_DIM, 2048, 0, 0, 16, 0,
        nullptr, cnt, tok, wt, (long)T_TOK * I_DIM, (long)I_DIM * D_DIM, 0);
}

// round 9
// speedup vs baseline: 29.7298x; 1.1358x over previous
#include <cuda_runtime.h>
#include <cuda_bf16.h>
#include <math.h>
#include <stdint.h>

#define T_TOK 2048
#define D_DIM 2048
#define N_H   16
#define N_KVH 4
#define HD    128
#define N_E   8
#define I_DIM 1024

// ---------------- scratch (static device globals; allocation-free) ----------------
__device__ float g_xnorm[T_TOK * D_DIM];
__device__ float g_q[T_TOK * N_H * HD];
__device__ float g_k[T_TOK * N_KVH * HD];
__device__ float g_v[T_TOK * N_KVH * HD];
__device__ float g_attn[T_TOK * N_H * HD];
__device__ float g_x2[T_TOK * D_DIM];
__device__ float g_gbuf[N_E * T_TOK * I_DIM];
__device__ float g_ubuf[N_E * T_TOK * I_DIM];
__device__ int   g_cnt[N_E];
__device__ int   g_tok[N_E * T_TOK];
__device__ float g_wt[N_E * T_TOK];
__device__ float g_cos[T_TOK * 64];
__device__ float g_sin[T_TOK * 64];

// ---------------- bf16 split helpers ----------------
__device__ __forceinline__ uint32_t pack2bf(float x, float y, uint32_t& lo) {
    __nv_bfloat162 h2 = __floats2bfloat162_rn(x, y);
    float2 hf = __bfloat1622float2(h2);
    __nv_bfloat162 l2 = __floats2bfloat162_rn(x - hf.x, y - hf.y);
    lo = *reinterpret_cast<uint32_t*>(&l2);
    return *reinterpret_cast<uint32_t*>(&h2);
}

#define MMA_BF16(c0, c1, c2, c3, a0, a1, a2, a3, b0, b1)                         \
    asm volatile(                                                                \
        "mma.sync.aligned.m16n8k16.row.col.f32.bf16.bf16.f32 "                   \
        "{%0,%1,%2,%3}, {%4,%5,%6,%7}, {%8,%9}, {%0,%1,%2,%3};\n"                \
        : "+f"(c0), "+f"(c1), "+f"(c2), "+f"(c3)                                 \
        : "r"(a0), "r"(a1), "r"(a2), "r"(a3), "r"(b0), "r"(b1))

// ---------------- RMSNorm ----------------
__global__ void rmsnorm_kernel(const float* __restrict__ x, const float* __restrict__ w,
                               float* __restrict__ out) {
    int row = blockIdx.x, tid = threadIdx.x;
    const float4* xr = (const float4*)(x + (size_t)row * D_DIM);
    const float4* wr = (const float4*)w;
    float ss = 0.f;
#pragma unroll
    for (int p = 0; p < 2; ++p) {
        float4 v = xr[tid + p * 256];
        ss += v.x * v.x + v.y * v.y + v.z * v.z + v.w * v.w;
    }
#pragma unroll
    for (int o = 16; o; o >>= 1) ss += __shfl_xor_sync(0xffffffffu, ss, o);
    __shared__ float red[8];
    if ((tid & 31) == 0) red[tid >> 5] = ss;
    __syncthreads();
    float tot = 0.f;
#pragma unroll
    for (int i = 0; i < 8; ++i) tot += red[i];
    float inv = rsqrtf(tot * (1.0f / D_DIM) + 1e-6f);
    float4* o4 = (float4*)(out + (size_t)row * D_DIM);
#pragma unroll
    for (int p = 0; p < 2; ++p) {
        int i = tid + p * 256;
        float4 v = xr[i], wv = wr[i];
        o4[i] = make_float4(v.x * inv * wv.x, v.y * inv * wv.y,
                            v.z * inv * wv.z, v.w * inv * wv.w);
    }
}

// ---------------- bf16x3 tensor-core GEMM (conflict-free strides + prefetch) ----------------
// EPI: 0 = +bias store, 1 = +residual store, 2 = plain store, 3 = atomic scatter *weight
// NMAT: 1..3 output matrices selected by blockIdx.x bands (nb0, nb1).
#define APS 136
#define BPS 136
template <int EPI, bool GATHER, int NMAT>
__global__ void __launch_bounds__(256)
tgemm_kernel(const float* __restrict__ A,
             const float* __restrict__ Bm0, const float* __restrict__ Bm1,
             const float* __restrict__ Bm2,
             float* __restrict__ Cm0, float* __restrict__ Cm1, float* __restrict__ Cm2,
             const float* __restrict__ bi0, const float* __restrict__ bi1,
             const float* __restrict__ bi2,
             int M, int Kd, int N0a, int N1a, int N2a, int nb0, int nb1,
             const float* __restrict__ res,
             const int* __restrict__ cnt, const int* __restrict__ tok,
             const float* __restrict__ wt,
             long aBatch, long bBatch, long cBatch) {
    __shared__ uint32_t Ah[16 * APS], Al[16 * APS];  // [kpair][m]
    __shared__ uint32_t Bh[16 * BPS], Bl[16 * BPS];  // [kpair][n]
    const int e = blockIdx.z;
    const int Mcur = cnt ? cnt[e] : M;
    const int m0 = blockIdx.y * 128;
    if (m0 >= Mcur) return;
    int bx = blockIdx.x;
    const float* Bsel;
    float* Csel;
    const float* bsel;
    int N;
    if (NMAT == 1 || bx < nb0) {
        Bsel = Bm0; Csel = Cm0; bsel = bi0; N = N0a;
    } else if (NMAT == 2 || bx < nb0 + nb1) {
        bx -= nb0; Bsel = Bm1; Csel = Cm1; bsel = bi1; N = N1a;
    } else {
        bx -= nb0 + nb1; Bsel = Bm2; Csel = Cm2; bsel = bi2; N = N2a;
    }
    const int n0 = bx * 128;
    const float* Ab = A + (size_t)e * aBatch;
    const float* Bb = Bsel + (size_t)e * bBatch;
    float* Cb = Csel + (size_t)e * cBatch;
    const int* tokb = tok ? tok + e * T_TOK : nullptr;
    const int tid = threadIdx.x;
    const int lane = tid & 31, warp = tid >> 5;
    const int warp_m = (warp >> 2) * 64, warp_n = (warp & 3) * 32;
    const int gr = lane >> 2, gc = lane & 3;

    const int r0 = tid >> 3;
    const int ac4 = (tid & 7) << 2;
    int arow[4];
    bool av[4];
#pragma unroll
    for (int p = 0; p < 4; ++p) {
        int rg = m0 + r0 + p * 32;
        av[p] = rg < Mcur;
        arow[p] = av[p] ? (GATHER ? tokb[rg] : rg) : 0;
    }
    const int bkp = tid >> 5;          // B staging: kpair rows bkp, bkp+8
    const int bc4 = (tid & 31) << 2;

    float acc[4][4][4];
#pragma unroll
    for (int mt = 0; mt < 4; ++mt)
#pragma unroll
        for (int nt = 0; nt < 4; ++nt)
#pragma unroll
            for (int r = 0; r < 4; ++r) acc[mt][nt][r] = 0.f;

    // prefetch registers
    float4 aReg[4], bReg[4];
#pragma unroll
    for (int p = 0; p < 4; ++p)
        aReg[p] = av[p] ? *(const float4*)(Ab + (size_t)arow[p] * Kd + ac4)
                        : make_float4(0.f, 0.f, 0.f, 0.f);
#pragma unroll
    for (int p = 0; p < 2; ++p) {
        const float* brow = Bb + (size_t)(2 * (bkp + p * 8)) * N + n0 + bc4;
        bReg[2 * p] = *(const float4*)brow;
        bReg[2 * p + 1] = *(const float4*)(brow + N);
    }

    for (int kk = 0; kk < Kd; kk += 32) {
        // pack prefetched regs -> smem
#pragma unroll
        for (int p = 0; p < 4; ++p) {
            int row = r0 + p * 32;
            int kp = ac4 >> 1;
            uint32_t l0, l1;
            uint32_t h0 = pack2bf(aReg[p].x, aReg[p].y, l0);
            uint32_t h1 = pack2bf(aReg[p].z, aReg[p].w, l1);
            Ah[kp * APS + row] = h0;       Al[kp * APS + row] = l0;
            Ah[(kp + 1) * APS + row] = h1; Al[(kp + 1) * APS + row] = l1;
        }
#pragma unroll
        for (int p = 0; p < 2; ++p) {
            int kp = bkp + p * 8;
            float4 v0 = bReg[2 * p], v1 = bReg[2 * p + 1];
            uint32_t h0, h1, h2, h3, l0, l1, l2, l3;
            h0 = pack2bf(v0.x, v1.x, l0);
            h1 = pack2bf(v0.y, v1.y, l1);
            h2 = pack2bf(v0.z, v1.z, l2);
            h3 = pack2bf(v0.w, v1.w, l3);
            *(uint4*)&Bh[kp * BPS + bc4] = make_uint4(h0, h1, h2, h3);
            *(uint4*)&Bl[kp * BPS + bc4] = make_uint4(l0, l1, l2, l3);
        }
        __syncthreads();
        // issue next tile's LDGs (overlap with MMAs below)
        if (kk + 32 < Kd) {
#pragma unroll
            for (int p = 0; p < 4; ++p)
                aReg[p] = av[p] ? *(const float4*)(Ab + (size_t)arow[p] * Kd + kk + 32 + ac4)
                                : make_float4(0.f, 0.f, 0.f, 0.f);
#pragma unroll
            for (int p = 0; p < 2; ++p) {
                const float* brow = Bb + (size_t)(kk + 32 + 2 * (bkp + p * 8)) * N + n0 + bc4;
                bReg[2 * p] = *(const float4*)brow;
                bReg[2 * p + 1] = *(const float4*)(brow + N);
            }
        }
#pragma unroll
        for (int s = 0; s < 2; ++s) {
            const int kpb = s * 8;
            uint32_t ah[4][4], al[4][4];
#pragma unroll
            for (int mt = 0; mt < 4; ++mt) {
                int m = warp_m + mt * 16 + gr;
                int i0 = (kpb + gc) * APS + m, i1 = (kpb + gc + 4) * APS + m;
                ah[mt][0] = Ah[i0];     ah[mt][1] = Ah[i0 + 8];
                ah[mt][2] = Ah[i1];     ah[mt][3] = Ah[i1 + 8];
                al[mt][0] = Al[i0];     al[mt][1] = Al[i0 + 8];
                al[mt][2] = Al[i1];     al[mt][3] = Al[i1 + 8];
            }
            uint32_t bh[4][2], bl[4][2];
#pragma unroll
            for (int nt = 0; nt < 4; ++nt) {
                int n = warp_n + nt * 8 + gr;
                bh[nt][0] = Bh[(kpb + gc) * BPS + n];
                bh[nt][1] = Bh[(kpb + gc + 4) * BPS + n];
                bl[nt][0] = Bl[(kpb + gc) * BPS + n];
                bl[nt][1] = Bl[(kpb + gc + 4) * BPS + n];
            }
#pragma unroll
            for (int mt = 0; mt < 4; ++mt)
#pragma unroll
                for (int nt = 0; nt < 4; ++nt) {
                    float* c = acc[mt][nt];
                    MMA_BF16(c[0], c[1], c[2], c[3],
                             ah[mt][0], ah[mt][1], ah[mt][2], ah[mt][3],
                             bl[nt][0], bl[nt][1]);
                    MMA_BF16(c[0], c[1], c[2], c[3],
                             al[mt][0], al[mt][1], al[mt][2], al[mt][3],
                             bh[nt][0], bh[nt][1]);
                    MMA_BF16(c[0], c[1], c[2], c[3],
                             ah[mt][0], ah[mt][1], ah[mt][2], ah[mt][3],
                             bh[nt][0], bh[nt][1]);
                }
        }
        __syncthreads();
    }

#pragma unroll
    for (int mt = 0; mt < 4; ++mt) {
#pragma unroll
        for (int rr = 0; rr < 2; ++rr) {
            int rg = m0 + warp_m + mt * 16 + gr + rr * 8;
            if (rg >= Mcur) continue;
            if (EPI == 3) {
                int t = tokb[rg];
                float w = wt[e * T_TOK + rg];
                float* outr = Cm0 + (size_t)t * N;
#pragma unroll
                for (int nt = 0; nt < 4; ++nt) {
                    int cb = n0 + warp_n + nt * 8 + gc * 2;
                    atomicAdd(&outr[cb], acc[mt][nt][rr * 2] * w);
                    atomicAdd(&outr[cb + 1], acc[mt][nt][rr * 2 + 1] * w);
                }
            } else {
#pragma unroll
                for (int nt = 0; nt < 4; ++nt) {
                    int cb = n0 + warp_n + nt * 8 + gc * 2;
                    float v0 = acc[mt][nt][rr * 2], v1 = acc[mt][nt][rr * 2 + 1];
                    if (EPI == 0) { v0 += bsel[cb]; v1 += bsel[cb + 1]; }
                    if (EPI == 1) {
                        const float* rrow = res + (size_t)rg * N;
                        v0 += rrow[cb]; v1 += rrow[cb + 1];
                    }
                    *(float2*)(Cb + (size_t)rg * N + cb) = make_float2(v0, v1);
                }
            }
        }
    }
}

// ---------------- RoPE: accurate table (double trig) + f32 apply ----------------
__global__ void rope_table_kernel(const int* __restrict__ pos,
                                  float* __restrict__ ctab, float* __restrict__ stab) {
    int t = blockIdx.x, i = threadIdx.x;  // 64 threads
    float p = (float)pos[t];
    float invf = (float)exp(-(double)i * (13.815510557964274 / 64.0));
    float fr = p * invf;
    double cd = cos((double)fr), sd = sin((double)fr);
    ctab[t * 64 + i] = (float)cd;
    stab[t * 64 + i] = (float)sd;
}

__global__ void rope_apply_kernel(float* __restrict__ x, const float* __restrict__ ctab,
                                  const float* __restrict__ stab, int nheads) {
    int t = blockIdx.x, h = blockIdx.y, i = threadIdx.x;  // 64 threads
    float c = ctab[t * 64 + i], s = stab[t * 64 + i];
    float* b = x + ((size_t)t * nheads + h) * HD;
    float x1 = b[i], x2 = b[i + 64];
    b[i] = x1 * c - x2 * s;
    b[i + 64] = x2 * c + x1 * s;
}

// ---------------- flash attention v4: bf16x3 tensor cores, validated softmax ----------------
#define QPS 69    // [dpair][row/key] stride (uint32)
#define VPS 132   // [keypair][d] stride (uint32)
#define SST 68    // S scratch stride (float)
#define PPS 69    // [keypair][row] stride (uint32)
__global__ void __launch_bounds__(256)
flash4_kernel(const float* __restrict__ q, const float* __restrict__ k,
              const float* __restrict__ v, float* __restrict__ o) {
    extern __shared__ uint32_t sm4[];
    uint32_t* Qh = sm4;                    // 64*QPS
    uint32_t* Ql = Qh + 64 * QPS;
    uint32_t* Kh = Ql + 64 * QPS;          // K [dpair][key]; reused as V [keypair][d]
    uint32_t* Kl = Kh + 64 * QPS;
    float* Ss = (float*)(Kl + 64 * QPS);   // 64*SST
    uint32_t* Ph = (uint32_t*)(Ss + 64 * SST);  // 32*PPS
    uint32_t* Pl = Ph + 32 * PPS;
    float* salpha = (float*)(Pl + 32 * PPS);    // 64
    const int tid = threadIdx.x;
    const int lane = tid & 31, warp = tid >> 5;
    const int gr = lane >> 2, gc = lane & 3;
    const int wms = (warp >> 1) * 16;
    const int wns = (warp & 1) * 32;
    const int wno = (warp & 1) * 64;
    const int sr = tid >> 2, sg = tid & 3;
    const int qt = blockIdx.x, head = blockIdx.y, kvh = head >> 2;
    const int qr0 = qt * 64;
    const float scale = 0.08838834764831845f;

#pragma unroll
    for (int p = 0; p < 8; ++p) {
        int idx = tid + p * 256;
        int row = idx >> 5, c4 = (idx & 31) << 2;
        float4 vq = *(const float4*)(q + (size_t)(qr0 + row) * (N_H * HD) + head * HD + c4);
        int dp = c4 >> 1;
        uint32_t l0, l1;
        uint32_t h0 = pack2bf(vq.x, vq.y, l0);
        uint32_t h1 = pack2bf(vq.z, vq.w, l1);
        Qh[dp * QPS + row] = h0;       Ql[dp * QPS + row] = l0;
        Qh[(dp + 1) * QPS + row] = h1; Ql[(dp + 1) * QPS + row] = l1;
    }
    float oacc[8][4];
#pragma unroll
    for (int nt = 0; nt < 8; ++nt)
#pragma unroll
        for (int r = 0; r < 4; ++r) oacc[nt][r] = 0.f;
    float mrow = -INFINITY, lrow = 0.f;

    for (int kt = 0; kt <= qt; ++kt) {
        const int kr0 = kt * 64;
        __syncthreads();
#pragma unroll
        for (int p = 0; p < 8; ++p) {
            int idx = tid + p * 256;
            int key = idx >> 5, c4 = (idx & 31) << 2;
            float4 vk = *(const float4*)(k + (size_t)(kr0 + key) * (N_KVH * HD) + kvh * HD + c4);
            int dp = c4 >> 1;
            uint32_t l0, l1;
            uint32_t h0 = pack2bf(vk.x, vk.y, l0);
            uint32_t h1 = pack2bf(vk.z, vk.w, l1);
            Kh[dp * QPS + key] = h0;       Kl[dp * QPS + key] = l0;
            Kh[(dp + 1) * QPS + key] = h1; Kl[(dp + 1) * QPS + key] = l1;
        }
        __syncthreads();
        float sc[4][4];
#pragma unroll
        for (int nt = 0; nt < 4; ++nt)
#pragma unroll
            for (int r = 0; r < 4; ++r) sc[nt][r] = 0.f;
#pragma unroll
        for (int ks = 0; ks < 8; ++ks) {
            const int kpb = ks * 8;
            uint32_t ah[4], al[4];
            {
                int m = wms + gr;
                int i0 = (kpb + gc) * QPS + m, i1 = (kpb + gc + 4) * QPS + m;
                ah[0] = Qh[i0]; ah[1] = Qh[i0 + 8]; ah[2] = Qh[i1]; ah[3] = Qh[i1 + 8];
                al[0] = Ql[i0]; al[1] = Ql[i0 + 8]; al[2] = Ql[i1]; al[3] = Ql[i1 + 8];
            }
#pragma unroll
            for (int nt = 0; nt < 4; ++nt) {
                int n = wns + nt * 8 + gr;
                uint32_t bh0 = Kh[(kpb + gc) * QPS + n];
                uint32_t bh1 = Kh[(kpb + gc + 4) * QPS + n];
                uint32_t bl0 = Kl[(kpb + gc) * QPS + n];
                uint32_t bl1 = Kl[(kpb + gc + 4) * QPS + n];
                float* c = sc[nt];
                MMA_BF16(c[0], c[1], c[2], c[3], ah[0], ah[1], ah[2], ah[3], bl0, bl1);
                MMA_BF16(c[0], c[1], c[2], c[3], al[0], al[1], al[2], al[3], bh0, bh1);
                MMA_BF16(c[0], c[1], c[2], c[3], ah[0], ah[1], ah[2], ah[3], bh0, bh1);
            }
        }
#pragma unroll
        for (int nt = 0; nt < 4; ++nt) {
            int cb = wns + nt * 8 + gc * 2;
            *(float2*)&Ss[(wms + gr) * SST + cb] = make_float2(sc[nt][0], sc[nt][1]);
            *(float2*)&Ss[(wms + gr + 8) * SST + cb] = make_float2(sc[nt][2], sc[nt][3]);
        }
        __syncthreads();
#pragma unroll
        for (int p = 0; p < 4; ++p) {
            int idx = tid + p * 256;
            int kp = idx >> 5, c4 = (idx & 31) << 2;
            const float* vrow = v + (size_t)(kr0 + 2 * kp) * (N_KVH * HD) + kvh * HD + c4;
            float4 v0 = *(const float4*)vrow;
            float4 v1 = *(const float4*)(vrow + N_KVH * HD);
            uint32_t h0, h1, h2, h3, l0, l1, l2, l3;
            h0 = pack2bf(v0.x, v1.x, l0);
            h1 = pack2bf(v0.y, v1.y, l1);
            h2 = pack2bf(v0.z, v1.z, l2);
            h3 = pack2bf(v0.w, v1.w, l3);
            *(uint4*)&Kh[kp * VPS + c4] = make_uint4(h0, h1, h2, h3);
            *(uint4*)&Kl[kp * VPS + c4] = make_uint4(l0, l1, l2, l3);
        }
        {
            float s[16];
#pragma unroll
            for (int jj = 0; jj < 16; ++jj) s[jj] = Ss[sr * SST + sg * 16 + jj];
            float mx = -INFINITY;
#pragma unroll
            for (int jj = 0; jj < 16; ++jj) {
                int col = kr0 + sg * 16 + jj;
                float sv = (col <= qr0 + sr) ? s[jj] * scale : -INFINITY;
                s[jj] = sv;
                mx = fmaxf(mx, sv);
            }
            mx = fmaxf(mx, __shfl_xor_sync(0xffffffffu, mx, 1));
            mx = fmaxf(mx, __shfl_xor_sync(0xffffffffu, mx, 2));
            float nm = fmaxf(mrow, mx);
            float rs = 0.f;
#pragma unroll
            for (int jj = 0; jj < 16; ++jj) {
                s[jj] = expf(s[jj] - nm);
                rs += s[jj];
            }
#pragma unroll
            for (int qq = 0; qq < 8; ++qq) {
                uint32_t lo;
                uint32_t hi = pack2bf(s[2 * qq], s[2 * qq + 1], lo);
                Ph[(sg * 8 + qq) * PPS + sr] = hi;
                Pl[(sg * 8 + qq) * PPS + sr] = lo;
            }
            rs += __shfl_xor_sync(0xffffffffu, rs, 1);
            rs += __shfl_xor_sync(0xffffffffu, rs, 2);
            float alpha = expf(mrow - nm);
            lrow = lrow * alpha + rs;
            mrow = nm;
            if (sg == 0) salpha[sr] = alpha;
        }
        __syncthreads();
        {
            float a0 = salpha[wms + gr], a1 = salpha[wms + gr + 8];
#pragma unroll
            for (int nt = 0; nt < 8; ++nt) {
                oacc[nt][0] *= a0; oacc[nt][1] *= a0;
                oacc[nt][2] *= a1; oacc[nt][3] *= a1;
            }
        }
#pragma unroll
        for (int ks = 0; ks < 4; ++ks) {
            const int kpb = ks * 8;
            uint32_t ah[4], al[4];
            {
                int m = wms + gr;
                int i0 = (kpb + gc) * PPS + m, i1 = (kpb + gc + 4) * PPS + m;
                ah[0] = Ph[i0]; ah[1] = Ph[i0 + 8]; ah[2] = Ph[i1]; ah[3] = Ph[i1 + 8];
                al[0] = Pl[i0]; al[1] = Pl[i0 + 8]; al[2] = Pl[i1]; al[3] = Pl[i1 + 8];
            }
#pragma unroll
            for (int nt = 0; nt < 8; ++nt) {
                int n = wno + nt * 8 + gr;
                uint32_t bh0 = Kh[(kpb + gc) * VPS + n];
                uint32_t bh1 = Kh[(kpb + gc + 4) * VPS + n];
                uint32_t bl0 = Kl[(kpb + gc) * VPS + n];
                uint32_t bl1 = Kl[(kpb + gc + 4) * VPS + n];
                float* c = oacc[nt];
                MMA_BF16(c[0], c[1], c[2], c[3], ah[0], ah[1], ah[2], ah[3], bl0, bl1);
                MMA_BF16(c[0], c[1], c[2], c[3], al[0], al[1], al[2], al[3], bh0, bh1);
                MMA_BF16(c[0], c[1], c[2], c[3], ah[0], ah[1], ah[2], ah[3], bh0, bh1);
            }
        }
    }
    __syncthreads();
    if (sg == 0) salpha[sr] = 1.f / lrow;
    __syncthreads();
    float i0 = salpha[wms + gr], i1 = salpha[wms + gr + 8];
#pragma unroll
    for (int nt = 0; nt < 8; ++nt) {
        int cb = head * HD + wno + nt * 8 + gc * 2;
        *(float2*)(o + (size_t)(qr0 + wms + gr) * (N_H * HD) + cb) =
            make_float2(oacc[nt][0] * i0, oacc[nt][1] * i0);
        *(float2*)(o + (size_t)(qr0 + wms + gr + 8) * (N_H * HD) + cb) =
            make_float2(oacc[nt][2] * i1, oacc[nt][3] * i1);
    }
}

// ---------------- router: logits -> softmax -> top2 -> scatter ----------------
__global__ void router_kernel(const float* __restrict__ x, const float* __restrict__ gw,
                              int* __restrict__ cnt, int* __restrict__ tok,
                              float* __restrict__ wt) {
    int t = blockIdx.x;
    const float* xr = x + (size_t)t * D_DIM;
    float acc[8] = {0, 0, 0, 0, 0, 0, 0, 0};
    for (int d = threadIdx.x; d < D_DIM; d += 256) {
        float xv = xr[d];
        const float4* g4 = (const float4*)(gw + (size_t)d * N_E);
        float4 a = g4[0], b = g4[1];
        acc[0] = fmaf(xv, a.x, acc[0]); acc[1] = fmaf(xv, a.y, acc[1]);
        acc[2] = fmaf(xv, a.z, acc[2]); acc[3] = fmaf(xv, a.w, acc[3]);
        acc[4] = fmaf(xv, b.x, acc[4]); acc[5] = fmaf(xv, b.y, acc[5]);
        acc[6] = fmaf(xv, b.z, acc[6]); acc[7] = fmaf(xv, b.w, acc[7]);
    }
    __shared__ float smr[8][256];
#pragma unroll
    for (int e = 0; e < 8; ++e) smr[e][threadIdx.x] = acc[e];
    __syncthreads();
    for (int s = 128; s; s >>= 1) {
        if (threadIdx.x < s)
#pragma unroll
            for (int e = 0; e < 8; ++e) smr[e][threadIdx.x] += smr[e][threadIdx.x + s];
        __syncthreads();
    }
    if (threadIdx.x == 0) {
        float l[8], p[8];
        float mx = -1e30f;
#pragma unroll
        for (int e = 0; e < 8; ++e) { l[e] = smr[e][0]; mx = fmaxf(mx, l[e]); }
        float ssum = 0.f;
#pragma unroll
        for (int e = 0; e < 8; ++e) { p[e] = expf(l[e] - mx); ssum += p[e]; }
#pragma unroll
        for (int e = 0; e < 8; ++e) p[e] /= ssum;
        int i0 = 0; float p0 = p[0];
#pragma unroll
        for (int e = 1; e < 8; ++e) if (p[e] > p0) { p0 = p[e]; i0 = e; }
        int i1 = -1; float p1 = -1.f;
#pragma unroll
        for (int e = 0; e < 8; ++e) if (e != i0 && p[e] > p1) { p1 = p[e]; i1 = e; }
        float wn = p0 + p1;
        int pos = atomicAdd(&cnt[i0], 1);
        tok[i0 * T_TOK + pos] = t; wt[i0 * T_TOK + pos] = p0 / wn;
        pos = atomicAdd(&cnt[i1], 1);
        tok[i1 * T_TOK + pos] = t; wt[i1 * T_TOK + pos] = p1 / wn;
    }
}

// ---------------- silu(g)*u, only over active rows per expert ----------------
__global__ void silu_mul_kernel(float* __restrict__ g, const float* __restrict__ u,
                                const int* __restrict__ cnt) {
    int e = blockIdx.z;
    int row = blockIdx.y;
    if (row >= cnt[e]) return;
    size_t base = ((size_t)e * T_TOK + row) * I_DIM;
    int i = blockIdx.x * 256 + threadIdx.x;
    float4 gv = ((const float4*)(g + base))[i];
    float4 uv = ((const float4*)(u + base))[i];
    gv.x = gv.x / (1.f + __expf(-gv.x)) * uv.x;
    gv.y = gv.y / (1.f + __expf(-gv.y)) * uv.y;
    gv.z = gv.z / (1.f + __expf(-gv.z)) * uv.z;
    gv.w = gv.w / (1.f + __expf(-gv.w)) * uv.w;
    ((float4*)(g + base))[i] = gv;
}

// ---------------- launch ----------------
extern "C" void kernel_launch(void* const* d_in, const int* in_sizes, int n_in,
                              void* d_out, int out_size) {
    const float* hidden = (const float*)d_in[0];
    const int* positions = (const int*)d_in[1];
    const float* ln1 = (const float*)d_in[2];
    const float* ln2 = (const float*)d_in[3];
    const float* wq = (const float*)d_in[4];
    const float* bq = (const float*)d_in[5];
    const float* wk = (const float*)d_in[6];
    const float* bk = (const float*)d_in[7];
    const float* wv = (const float*)d_in[8];
    const float* bv = (const float*)d_in[9];
    const float* wo = (const float*)d_in[10];
    const float* gate_w = (const float*)d_in[11];
    const float* w_gate = (const float*)d_in[12];
    const float* w_up = (const float*)d_in[13];
    const float* w_down = (const float*)d_in[14];
    float* out = (float*)d_out;

    float *xnorm, *q, *k, *v, *attn, *x2, *gbuf, *ubuf, *wt, *ctab, *stab;
    int *cnt, *tok;
    cudaGetSymbolAddress((void**)&xnorm, g_xnorm);
    cudaGetSymbolAddress((void**)&q, g_q);
    cudaGetSymbolAddress((void**)&k, g_k);
    cudaGetSymbolAddress((void**)&v, g_v);
    cudaGetSymbolAddress((void**)&attn, g_attn);
    cudaGetSymbolAddress((void**)&x2, g_x2);
    cudaGetSymbolAddress((void**)&gbuf, g_gbuf);
    cudaGetSymbolAddress((void**)&ubuf, g_ubuf);
    cudaGetSymbolAddress((void**)&cnt, g_cnt);
    cudaGetSymbolAddress((void**)&tok, g_tok);
    cudaGetSymbolAddress((void**)&wt, g_wt);
    cudaGetSymbolAddress((void**)&ctab, g_cos);
    cudaGetSymbolAddress((void**)&stab, g_sin);

    const int smem_f4 = (4 * 64 * QPS + 64 * SST + 2 * 32 * PPS + 64) * 4;
    cudaFuncSetAttribute(flash4_kernel, cudaFuncAttributeMaxDynamicSharedMemorySize, smem_f4);

    // 0) RoPE table (accurate trig)
    rope_table_kernel<<<T_TOK, 64>>>(positions, ctab, stab);
    // 1) RMSNorm 1
    rmsnorm_kernel<<<T_TOK, 256>>>(hidden, ln1, xnorm);
    // 2) fused QKV projection (+bias): 16+4+4 n-blocks
    tgemm_kernel<0, false, 3><<<dim3(24, 16, 1), 256>>>(
        xnorm, wq, wk, wv, q, k, v, bq, bk, bv,
        T_TOK, D_DIM, 2048, 512, 512, 16, 4,
        nullptr, nullptr, nullptr, nullptr, 0, 0, 0);
    // 3) RoPE apply
    rope_apply_kernel<<<dim3(T_TOK, N_H), 64>>>(q, ctab, stab, N_H);
    rope_apply_kernel<<<dim3(T_TOK, N_KVH), 64>>>(k, ctab, stab, N_KVH);
    // 4) attention (bf16x3 tensor cores)
    flash4_kernel<<<dim3(T_TOK / 64, N_H), 256, smem_f4>>>(q, k, v, attn);
    // 5) output proj + residual -> d_out holds h
    tgemm_kernel<1, false, 1><<<dim3(16, 16, 1), 256>>>(
        attn, wo, nullptr, nullptr, out, nullptr, nullptr, nullptr, nullptr, nullptr,
        T_TOK, 2048, 2048, 0, 0, 16, 0,
        hidden, nullptr, nullptr, nullptr, 0, 0, 0);
    // 6) RMSNorm 2
    rmsnorm_kernel<<<T_TOK, 256>>>(out, ln2, x2);
    // 7) router
    cudaMemsetAsync(cnt, 0, N_E * sizeof(int));
    router_kernel<<<T_TOK, 256>>>(x2, gate_w, cnt, tok, wt);
    // 8) expert gate+up fused (gathered rows, early-exit on count)
    tgemm_kernel<2, true, 2><<<dim3(16, 16, N_E), 256>>>(
        x2, w_gate, w_up, nullptr, gbuf, ubuf, nullptr, nullptr, nullptr, nullptr,
        0, D_DIM, 1024, 1024, 0, 8, 8,
        nullptr, cnt, tok, nullptr, 0, (long)D_DIM * I_DIM, (long)T_TOK * I_DIM);
    // 9) silu(g)*u on active rows only
    silu_mul_kernel<<<dim3(1, T_TOK, N_E), 256>>>(gbuf, ubuf, cnt);
    // 10) expert down GEMM, scatter *weight into d_out (residual already there)
    tgemm_kernel<3, false, 1><<<dim3(16, 16, N_E), 256>>>(
        gbuf, w_down, nullptr, nullptr, out, nullptr, nullptr, nullptr, nullptr, nullptr,
        0, I_DIM, 2048, 0, 0, 16, 0,
        nullptr, cnt, tok, wt, (long)T_TOK * I_DIM, (long)I_DIM * D_DIM, 0);
}